// round 8
// baseline (speedup 1.0000x reference)
#include <cuda_runtime.h>
#include <cstdint>

// ---------------------------------------------------------------------------
// VQ-VAE forward, sm_100a. Round 7: encoder 3x3 = proven fp32 big-tile;
// decoder 3x3 = 3xTF32 mma (diagnostic: no argmin downstream of decoder).
// ---------------------------------------------------------------------------

#define NB 16

__device__ float g_bufA[(size_t)NB * 64 * 128 * 128];
__device__ float g_bufB[(size_t)NB * 128 * 64 * 64];
__device__ float g_bufC[(size_t)NB * 128 * 64 * 64];
__device__ float g_half[(size_t)NB * 64 * 64 * 64];
__device__ float g_z[(size_t)NB * 64 * 64 * 64];
__device__ float g_q[(size_t)NB * 64 * 64 * 64];
__device__ float g_d1[(size_t)NB * 64 * 64 * 64];
__device__ float g_d2[(size_t)NB * 64 * 64 * 64];
__device__ float g_e[(size_t)NB * 32 * 128 * 128];
__device__ double g_vq_loss;
__device__ double g_rec_loss;

__global__ void zero_losses_kernel() {
    g_vq_loss = 0.0;
    g_rec_loss = 0.0;
}

// ---------------------------------------------------------------------------
// fp32 big-tile 3x3 conv (round-4, proven). Block 256 (16x16).
// Block tile: 32 rows x 64 cols x 8 co. Thread: 2x4 out x 8 co.
// grid = (2, Co/8, N)
// ---------------------------------------------------------------------------
#define C3_SMEM ((8 * 34 * 68 + 8 * 8 * 12) * 4)

template <bool RELU, bool BIAS>
__global__ void __launch_bounds__(256, 2) conv3x3_big(
    const float* __restrict__ in, const float* __restrict__ w,
    const float* __restrict__ bias, float* __restrict__ out,
    int Ci, int Co)
{
    extern __shared__ float sm[];
    float (*sIn)[34][68] = reinterpret_cast<float(*)[34][68]>(sm);
    float (*sW)[8][12] = reinterpret_cast<float(*)[8][12]>(sm + 8 * 34 * 68);

    const int n = blockIdx.z;
    const int cog = blockIdx.y;
    const int oh0 = blockIdx.x * 32;
    const int t = threadIdx.x;
    const int tx = t & 15, ty = t >> 4;

    if (t < 34) {
        #pragma unroll
        for (int ci = 0; ci < 8; ci++) {
            sIn[ci][t][0] = 0.0f;
            sIn[ci][t][65] = 0.0f;
        }
    }

    float acc[8][8];
    #pragma unroll
    for (int i = 0; i < 8; i++)
        #pragma unroll
        for (int j = 0; j < 8; j++) acc[i][j] = 0.0f;

    const float* inb = in + (size_t)n * Ci * 4096;
    const int c64 = t & 63;
    const int r4 = t >> 6;

    for (int cb = 0; cb < Ci; cb += 8) {
        __syncthreads();
        #pragma unroll
        for (int ci = 0; ci < 8; ci++) {
            const float* g = inb + (size_t)(cb + ci) * 4096 + c64;
            #pragma unroll
            for (int rb = 0; rb < 36; rb += 4) {
                const int r = rb + r4;
                if (r < 34) {
                    const int ih = oh0 - 1 + r;
                    float v = 0.0f;
                    if (ih >= 0 && ih < 64) v = g[ih * 64];
                    sIn[ci][r][c64 + 1] = v;
                }
            }
        }
        for (int i = t; i < 576; i += 256) {
            const int co = i / 72;
            const int rem = i - co * 72;
            const int ci = rem / 9;
            const int k = rem - ci * 9;
            sW[co][ci][k] = w[(((size_t)(cog * 8 + co)) * Ci + cb + ci) * 9 + k];
        }
        __syncthreads();

        #pragma unroll 1
        for (int ci = 0; ci < 8; ci++) {
            float iv[4][6];
            #pragma unroll
            for (int r = 0; r < 4; r++) {
                const float* rp = &sIn[ci][2 * ty + r][4 * tx];
                const float4 a = *reinterpret_cast<const float4*>(rp);
                const float2 b = *reinterpret_cast<const float2*>(rp + 4);
                iv[r][0] = a.x; iv[r][1] = a.y; iv[r][2] = a.z;
                iv[r][3] = a.w; iv[r][4] = b.x; iv[r][5] = b.y;
            }
            #pragma unroll
            for (int co = 0; co < 8; co++) {
                const float4* wq = reinterpret_cast<const float4*>(&sW[co][ci][0]);
                const float4 w0 = wq[0], w1 = wq[1];
                const float w8 = sW[co][ci][8];
                const float wv[9] = {w0.x, w0.y, w0.z, w0.w,
                                     w1.x, w1.y, w1.z, w1.w, w8};
                #pragma unroll
                for (int r2 = 0; r2 < 2; r2++)
                    #pragma unroll
                    for (int c2 = 0; c2 < 4; c2++) {
                        float a = acc[co][r2 * 4 + c2];
                        #pragma unroll
                        for (int kh = 0; kh < 3; kh++)
                            #pragma unroll
                            for (int kw = 0; kw < 3; kw++)
                                a = fmaf(iv[r2 + kh][c2 + kw],
                                         wv[kh * 3 + kw], a);
                        acc[co][r2 * 4 + c2] = a;
                    }
            }
        }
    }

    float* outb = out + ((size_t)n * Co + cog * 8) * 4096;
    #pragma unroll
    for (int co = 0; co < 8; co++) {
        const float b = BIAS ? bias[cog * 8 + co] : 0.0f;
        #pragma unroll
        for (int r2 = 0; r2 < 2; r2++) {
            const int oh = oh0 + 2 * ty + r2;
            float4 v = make_float4(acc[co][r2 * 4 + 0] + b,
                                   acc[co][r2 * 4 + 1] + b,
                                   acc[co][r2 * 4 + 2] + b,
                                   acc[co][r2 * 4 + 3] + b);
            if (RELU) {
                v.x = fmaxf(v.x, 0.f); v.y = fmaxf(v.y, 0.f);
                v.z = fmaxf(v.z, 0.f); v.w = fmaxf(v.w, 0.f);
            }
            *reinterpret_cast<float4*>(
                outb + (size_t)co * 4096 + oh * 64 + 4 * tx) = v;
        }
    }
}

// ---------------------------------------------------------------------------
// 3xTF32 mma 3x3 conv (round-6 kernel, DECODER ONLY this round).
// ---------------------------------------------------------------------------
__device__ __forceinline__ uint32_t f2tf(float x) {
    uint32_t r;
    asm("cvt.rna.tf32.f32 %0, %1;" : "=r"(r) : "f"(x));
    return r;
}

__device__ __forceinline__ float2 tf32split(float x) {
    const uint32_t hib = f2tf(x);
    const float hif = __uint_as_float(hib);
    const uint32_t lob = f2tf(x - hif);
    return make_float2(hif, __uint_as_float(lob));
}

#define MMA_TF32(D, A0, A1, A2, A3, B0, B1)                                 \
    asm volatile(                                                           \
        "mma.sync.aligned.m16n8k8.row.col.f32.tf32.tf32.f32 "               \
        "{%0,%1,%2,%3}, {%4,%5,%6,%7}, {%8,%9}, {%0,%1,%2,%3};"             \
        : "+f"((D)[0]), "+f"((D)[1]), "+f"((D)[2]), "+f"((D)[3])            \
        : "r"(A0), "r"(A1), "r"(A2), "r"(A3), "r"(B0), "r"(B1))

#define C3MMA_SMEM(WM) \
    ((((8 / (WM)) + 2) * 8 * 69 + 8 * 9 * ((WM) * 32 + 1)) * 8)

template <int WM, bool RELU, bool BIAS>
__global__ void __launch_bounds__(256) conv3x3_mma(
    const float* __restrict__ in, const float* __restrict__ w,
    const float* __restrict__ bias, float* __restrict__ out,
    int Ci, int Co)
{
    constexpr int ROWS = 8 / WM;
    constexpr int CoB = WM * 32;
    extern __shared__ float2 sm2[];
    float2 (*sIn)[8][69] = reinterpret_cast<float2(*)[8][69]>(sm2);
    float2 (*sW)[9][CoB + 1] =
        reinterpret_cast<float2(*)[9][CoB + 1]>(sm2 + (ROWS + 2) * 8 * 69);

    const int n = blockIdx.z;
    const int cog = blockIdx.y;
    const int oh0 = blockIdx.x * ROWS;
    const int t = threadIdx.x;
    const int lane = t & 31;
    const int wid = t >> 5;
    const int wm = wid & (WM - 1);
    const int wn = wid / WM;
    const int grp = lane >> 2;
    const int tig = lane & 3;

    if (t < (ROWS + 2) * 8) {
        const int r = t >> 3, ci = t & 7;
        sIn[r][ci][0] = make_float2(0.0f, 0.0f);
        sIn[r][ci][65] = make_float2(0.0f, 0.0f);
    }

    float d[2][8][4];
    #pragma unroll
    for (int m = 0; m < 2; m++)
        #pragma unroll
        for (int j = 0; j < 8; j++)
            #pragma unroll
            for (int e = 0; e < 4; e++) d[m][j][e] = 0.0f;

    const float* inb = in + (size_t)n * Ci * 4096;
    const int c64 = t & 63, stripe = t >> 6;

    for (int cb = 0; cb < Ci; cb += 8) {
        __syncthreads();
        #pragma unroll
        for (int ci = 0; ci < 8; ci++) {
            const float* g = inb + (size_t)(cb + ci) * 4096 + c64;
            for (int r = stripe; r < ROWS + 2; r += 4) {
                const int ih = oh0 - 1 + r;
                float v = 0.0f;
                if (ih >= 0 && ih < 64) v = g[ih * 64];
                sIn[r][ci][c64 + 1] = tf32split(v);
            }
        }
        for (int i = t; i < CoB * 72; i += 256) {
            const int co = i / 72;
            const int rem = i - co * 72;
            const int ci = rem / 9;
            const int tap = rem - ci * 9;
            const float v =
                w[(((size_t)(cog * CoB + co)) * Ci + cb + ci) * 9 + tap];
            sW[ci][tap][co] = tf32split(v);
        }
        __syncthreads();

        #pragma unroll
        for (int tap = 0; tap < 9; tap++) {
            const int dh = tap / 3, dw = tap - dh * 3;
            uint32_t ah[2][4], al[2][4];
            #pragma unroll
            for (int m = 0; m < 2; m++) {
                const int co0 = wm * 32 + m * 16 + grp;
                const float2 w0 = sW[tig][tap][co0];
                const float2 w1 = sW[tig][tap][co0 + 8];
                const float2 w2 = sW[tig + 4][tap][co0];
                const float2 w3 = sW[tig + 4][tap][co0 + 8];
                ah[m][0] = __float_as_uint(w0.x); al[m][0] = __float_as_uint(w0.y);
                ah[m][1] = __float_as_uint(w1.x); al[m][1] = __float_as_uint(w1.y);
                ah[m][2] = __float_as_uint(w2.x); al[m][2] = __float_as_uint(w2.y);
                ah[m][3] = __float_as_uint(w3.x); al[m][3] = __float_as_uint(w3.y);
            }
            const int rr = wn + dh;
            #pragma unroll
            for (int j = 0; j < 8; j++) {
                const int cc = j * 8 + grp + dw;
                const float2 bA = sIn[rr][tig][cc];
                const float2 bB = sIn[rr][tig + 4][cc];
                const uint32_t bh0 = __float_as_uint(bA.x);
                const uint32_t bl0 = __float_as_uint(bA.y);
                const uint32_t bh1 = __float_as_uint(bB.x);
                const uint32_t bl1 = __float_as_uint(bB.y);
                #pragma unroll
                for (int m = 0; m < 2; m++) {
                    MMA_TF32(d[m][j], ah[m][0], ah[m][1], ah[m][2], ah[m][3],
                             bh0, bh1);
                    MMA_TF32(d[m][j], ah[m][0], ah[m][1], ah[m][2], ah[m][3],
                             bl0, bl1);
                    MMA_TF32(d[m][j], al[m][0], al[m][1], al[m][2], al[m][3],
                             bh0, bh1);
                }
            }
        }
    }

    const int oh = oh0 + wn;
    #pragma unroll
    for (int m = 0; m < 2; m++) {
        const int coA = cog * CoB + wm * 32 + m * 16 + grp;
        const float bA = BIAS ? bias[coA] : 0.0f;
        const float bB = BIAS ? bias[coA + 8] : 0.0f;
        #pragma unroll
        for (int j = 0; j < 8; j++) {
            const int col = j * 8 + 2 * tig;
            float2 v0 = make_float2(d[m][j][0] + bA, d[m][j][1] + bA);
            float2 v1 = make_float2(d[m][j][2] + bB, d[m][j][3] + bB);
            if (RELU) {
                v0.x = fmaxf(v0.x, 0.f); v0.y = fmaxf(v0.y, 0.f);
                v1.x = fmaxf(v1.x, 0.f); v1.y = fmaxf(v1.y, 0.f);
            }
            *reinterpret_cast<float2*>(
                out + ((size_t)(n * Co + coA) * 64 + oh) * 64 + col) = v0;
            *reinterpret_cast<float2*>(
                out + ((size_t)(n * Co + coA + 8) * 64 + oh) * 64 + col) = v1;
        }
    }
}

// ---------------------------------------------------------------------------
// 4x4 conv, stride 2, pad 1 (fp32).
// ---------------------------------------------------------------------------
#define K4_SMEM ((4 * 66 * 68 + 8 * 4 * 16) * 4)

__global__ void __launch_bounds__(256) conv4x4s2_tiled(
    const float* __restrict__ in, const float* __restrict__ w,
    const float* __restrict__ bias, float* __restrict__ out,
    int Ci, int Hi, int Wi, int Co, int Ho, int Wo)
{
    extern __shared__ float sm[];
    float (*sIn)[66][68] = reinterpret_cast<float(*)[66][68]>(sm);
    float* sWp = sm + 4 * 66 * 68;

    const int n = blockIdx.z;
    const int cog = blockIdx.y;
    const int ntx = Wo >> 5;
    const int tileY = blockIdx.x / ntx;
    const int tileX = blockIdx.x - tileY * ntx;
    const int oh0 = tileY * 32, ow0 = tileX * 32;
    const int t = threadIdx.x;
    const int tx = t & 15, ty = t >> 4;

    float acc[8][4];
    #pragma unroll
    for (int i = 0; i < 8; i++)
        #pragma unroll
        for (int j = 0; j < 4; j++) acc[i][j] = 0.0f;

    const float* inb = in + (size_t)n * Ci * Hi * Wi;

    for (int cb = 0; cb < Ci; cb += 4) {
        __syncthreads();
        for (int i = t; i < 4 * 66 * 66; i += 256) {
            const int ci = i / 4356;
            const int rem = i - ci * 4356;
            const int r = rem / 66;
            const int c = rem - r * 66;
            const int ih = oh0 * 2 - 1 + r;
            const int iw = ow0 * 2 - 1 + c;
            const int cig = cb + ci;
            float v = 0.0f;
            if (cig < Ci && ih >= 0 && ih < Hi && iw >= 0 && iw < Wi)
                v = inb[(size_t)cig * Hi * Wi + ih * Wi + iw];
            sIn[ci][r][c] = v;
        }
        for (int i = t; i < 8 * 4 * 16; i += 256) {
            const int co = i >> 6;
            const int rem = i & 63;
            const int ci = rem >> 4;
            const int k = rem & 15;
            const int cig = cb + ci;
            sWp[i] = (cig < Ci)
                ? w[(((size_t)(cog * 8 + co)) * Ci + cig) * 16 + k] : 0.0f;
        }
        __syncthreads();

        #pragma unroll 1
        for (int ci = 0; ci < 4; ci++) {
            float iv[6][6];
            #pragma unroll
            for (int r = 0; r < 6; r++) {
                const float* rb = &sIn[ci][4 * ty + r][4 * tx];
                const float4 a = *reinterpret_cast<const float4*>(rb);
                const float2 b = *reinterpret_cast<const float2*>(rb + 4);
                iv[r][0] = a.x; iv[r][1] = a.y; iv[r][2] = a.z; iv[r][3] = a.w;
                iv[r][4] = b.x; iv[r][5] = b.y;
            }
            #pragma unroll
            for (int co = 0; co < 8; co++) {
                const float4* wq = reinterpret_cast<const float4*>(
                    sWp + (co * 4 + ci) * 16);
                const float4 q0 = wq[0], q1 = wq[1], q2 = wq[2], q3 = wq[3];
                float wv[16] = {q0.x, q0.y, q0.z, q0.w, q1.x, q1.y, q1.z, q1.w,
                                q2.x, q2.y, q2.z, q2.w, q3.x, q3.y, q3.z, q3.w};
                #pragma unroll
                for (int r2 = 0; r2 < 2; r2++)
                    #pragma unroll
                    for (int c2 = 0; c2 < 2; c2++) {
                        float a = acc[co][r2 * 2 + c2];
                        #pragma unroll
                        for (int kh = 0; kh < 4; kh++)
                            #pragma unroll
                            for (int kw = 0; kw < 4; kw++)
                                a = fmaf(iv[2 * r2 + kh][2 * c2 + kw],
                                         wv[kh * 4 + kw], a);
                        acc[co][r2 * 2 + c2] = a;
                    }
            }
        }
    }

    #pragma unroll
    for (int co = 0; co < 8; co++) {
        const float b = bias[cog * 8 + co];
        float* ob = out + ((size_t)n * Co + cog * 8 + co) * Ho * Wo;
        #pragma unroll
        for (int r2 = 0; r2 < 2; r2++) {
            const int oh = oh0 + 2 * ty + r2;
            *reinterpret_cast<float2*>(ob + (size_t)oh * Wo + ow0 + 2 * tx) =
                make_float2(acc[co][r2 * 2 + 0] + b, acc[co][r2 * 2 + 1] + b);
        }
    }
}

// ---------------------------------------------------------------------------
// 1x1 conv (fp32).
// ---------------------------------------------------------------------------
template <bool RELU, bool BIAS, bool RES>
__global__ void __launch_bounds__(256) conv1x1_k(
    const float* __restrict__ in, const float* __restrict__ w,
    const float* __restrict__ bias, const float* __restrict__ res,
    float* __restrict__ out, int Ci, int Co)
{
    __shared__ float sW1[8 * 128];
    const int n = blockIdx.z;
    const int cog = blockIdx.y;
    const int hw = blockIdx.x * 1024 + threadIdx.x * 4;
    const int t = threadIdx.x;

    for (int i = t; i < 8 * Ci; i += 256)
        sW1[i] = w[(size_t)cog * 8 * Ci + i];
    __syncthreads();

    const float* ip = in + (size_t)n * Ci * 4096 + hw;
    float4 acc[8];
    #pragma unroll
    for (int co = 0; co < 8; co++) acc[co] = make_float4(0.f, 0.f, 0.f, 0.f);

    #pragma unroll 2
    for (int ci = 0; ci < Ci; ci++) {
        const float4 xv = *reinterpret_cast<const float4*>(ip + (size_t)ci * 4096);
        #pragma unroll
        for (int co = 0; co < 8; co++) {
            const float wv = sW1[co * Ci + ci];
            acc[co].x = fmaf(xv.x, wv, acc[co].x);
            acc[co].y = fmaf(xv.y, wv, acc[co].y);
            acc[co].z = fmaf(xv.z, wv, acc[co].z);
            acc[co].w = fmaf(xv.w, wv, acc[co].w);
        }
    }

    #pragma unroll
    for (int co = 0; co < 8; co++) {
        float4 v = acc[co];
        if (BIAS) {
            const float b = bias[cog * 8 + co];
            v.x += b; v.y += b; v.z += b; v.w += b;
        }
        if (RELU) {
            v.x = fmaxf(v.x, 0.f); v.y = fmaxf(v.y, 0.f);
            v.z = fmaxf(v.z, 0.f); v.w = fmaxf(v.w, 0.f);
        }
        const size_t o = ((size_t)n * Co + cog * 8 + co) * 4096 + hw;
        if (RES) {
            const float4 r = *reinterpret_cast<const float4*>(res + o);
            v.x += r.x; v.y += r.y; v.z += r.z; v.w += r.w;
        }
        *reinterpret_cast<float4*>(out + o) = v;
    }
}

// ---------------------------------------------------------------------------
// Transposed conv k4 s2 p1 (fp32).
// ---------------------------------------------------------------------------
template <int CO_T>
__global__ void __launch_bounds__(256) deconv4x4s2_tiled(
    const float* __restrict__ in, const float* __restrict__ w,
    const float* __restrict__ bias, float* __restrict__ out,
    int Ci, int Hi, int Wi, int Co)
{
    __shared__ float sIn[8][18][36];
    __shared__ float sW[8 * CO_T * 16];

    const int n = blockIdx.z;
    const int cog = blockIdx.y;
    const int ntx = Wi >> 5;
    const int tileY = blockIdx.x / ntx;
    const int tileX = blockIdx.x - tileY * ntx;
    const int i0 = tileY * 16, j0 = tileX * 32;
    const int t = threadIdx.x;
    const int tx = t & 15, ty = t >> 4;

    float acc[CO_T][2][4];
    #pragma unroll
    for (int c = 0; c < CO_T; c++)
        #pragma unroll
        for (int a = 0; a < 2; a++)
            #pragma unroll
            for (int j = 0; j < 4; j++) acc[c][a][j] = 0.0f;

    const float* inb = in + (size_t)n * Ci * Hi * Wi;

    const int RR[2][2] = {{1, 0}, {2, 1}};
    const int KH[2][2] = {{1, 3}, {0, 2}};
    const int CC[2][2] = {{1, 0}, {2, 1}};
    const int KW[2][2] = {{1, 3}, {0, 2}};

    for (int cb = 0; cb < Ci; cb += 8) {
        __syncthreads();
        for (int i = t; i < 8 * 18 * 34; i += 256) {
            const int ci = i / 612;
            const int rem = i - ci * 612;
            const int r = rem / 34;
            const int c = rem - r * 34;
            const int ih = i0 - 1 + r;
            const int iw = j0 - 1 + c;
            float v = 0.0f;
            if (ih >= 0 && ih < Hi && iw >= 0 && iw < Wi)
                v = inb[(size_t)(cb + ci) * Hi * Wi + ih * Wi + iw];
            sIn[ci][r][c] = v;
        }
        for (int i = t; i < 8 * CO_T * 16; i += 256) {
            const int ci = i / (CO_T * 16);
            const int rem = i - ci * (CO_T * 16);
            const int co = rem >> 4;
            const int k = rem & 15;
            sW[i] = w[(((size_t)(cb + ci)) * Co + cog * CO_T + co) * 16 + k];
        }
        __syncthreads();

        #pragma unroll 1
        for (int ci = 0; ci < 8; ci++) {
            float iv[3][4];
            #pragma unroll
            for (int r = 0; r < 3; r++) {
                const float2* rp = reinterpret_cast<const float2*>(
                    &sIn[ci][ty + r][2 * tx]);
                const float2 a = rp[0], b = rp[1];
                iv[r][0] = a.x; iv[r][1] = a.y; iv[r][2] = b.x; iv[r][3] = b.y;
            }
            #pragma unroll
            for (int co = 0; co < CO_T; co++) {
                const float4* wq = reinterpret_cast<const float4*>(
                    sW + (ci * CO_T + co) * 16);
                const float4 q0 = wq[0], q1 = wq[1], q2 = wq[2], q3 = wq[3];
                float wv[16] = {q0.x, q0.y, q0.z, q0.w, q1.x, q1.y, q1.z, q1.w,
                                q2.x, q2.y, q2.z, q2.w, q3.x, q3.y, q3.z, q3.w};
                #pragma unroll
                for (int q = 0; q < 2; q++)
                    #pragma unroll
                    for (int a = 0; a < 2; a++)
                        #pragma unroll
                        for (int b = 0; b < 2; b++) {
                            float s = acc[co][a][2 * q + b];
                            #pragma unroll
                            for (int si = 0; si < 2; si++)
                                #pragma unroll
                                for (int ti = 0; ti < 2; ti++)
                                    s = fmaf(iv[RR[a][si]][q + CC[b][ti]],
                                             wv[KH[a][si] * 4 + KW[b][ti]], s);
                            acc[co][a][2 * q + b] = s;
                        }
            }
        }
    }

    const int Ho = 2 * Hi, Wo = 2 * Wi;
    const int ow = 2 * j0 + 4 * tx;
    #pragma unroll
    for (int co = 0; co < CO_T; co++) {
        const float b = bias[cog * CO_T + co];
        float* ob = out + ((size_t)n * Co + cog * CO_T + co) * Ho * Wo;
        #pragma unroll
        for (int a = 0; a < 2; a++) {
            const int oh = 2 * (i0 + ty) + a;
            *reinterpret_cast<float4*>(ob + (size_t)oh * Wo + ow) =
                make_float4(acc[co][a][0] + b, acc[co][a][1] + b,
                            acc[co][a][2] + b, acc[co][a][3] + b);
        }
    }
}

// ---------------------------------------------------------------------------
__device__ __forceinline__ float blockReduceSum(float v) {
    __shared__ float sh[32];
    #pragma unroll
    for (int o = 16; o > 0; o >>= 1) v += __shfl_down_sync(0xffffffffu, v, o);
    if ((threadIdx.x & 31) == 0) sh[threadIdx.x >> 5] = v;
    __syncthreads();
    const int nw = (blockDim.x + 31) >> 5;
    v = (threadIdx.x < (unsigned)nw) ? sh[threadIdx.x] : 0.0f;
    if (threadIdx.x < 32) {
        #pragma unroll
        for (int o = 16; o > 0; o >>= 1) v += __shfl_down_sync(0xffffffffu, v, o);
    }
    return v;
}

#define VQ_K 512
#define VQ_D 64
#define VQ_SMEM ((VQ_K * VQ_D + VQ_K) * 4)

__global__ void __launch_bounds__(256) vq_kernel(
    const float* __restrict__ z, const float* __restrict__ cb,
    float* __restrict__ q)
{
    extern __shared__ float smem[];
    float* scb = smem;
    float* snorm = smem + VQ_K * VQ_D;

    for (int i = threadIdx.x; i < VQ_K * VQ_D; i += blockDim.x)
        scb[i] = cb[i];
    __syncthreads();
    for (int c = threadIdx.x; c < VQ_K; c += blockDim.x) {
        float s = 0.0f;
        const float* cp = scb + c * VQ_D;
        #pragma unroll 16
        for (int d = 0; d < VQ_D; d++) s = fmaf(cp[d], cp[d], s);
        snorm[c] = s;
    }
    __syncthreads();

    const int pos = blockIdx.x * blockDim.x + threadIdx.x;
    const int n = pos >> 12;
    const int hw = pos & 4095;

    float zv[VQ_D];
    const float* zp = z + (size_t)n * VQ_D * 4096 + hw;
    float zn = 0.0f;
    #pragma unroll
    for (int d = 0; d < VQ_D; d++) {
        zv[d] = zp[(size_t)d * 4096];
        zn = fmaf(zv[d], zv[d], zn);
    }

    float bestd = 3.402823466e+38f;
    int besti = 0;
    for (int c = 0; c < VQ_K; c++) {
        const float4* cp4 = reinterpret_cast<const float4*>(scb + c * VQ_D);
        float dot = 0.0f;
        #pragma unroll
        for (int d4 = 0; d4 < VQ_D / 4; d4++) {
            const float4 cv = cp4[d4];
            dot = fmaf(zv[4 * d4 + 0], cv.x, dot);
            dot = fmaf(zv[4 * d4 + 1], cv.y, dot);
            dot = fmaf(zv[4 * d4 + 2], cv.z, dot);
            dot = fmaf(zv[4 * d4 + 3], cv.w, dot);
        }
        const float dist = zn - 2.0f * dot + snorm[c];
        if (dist < bestd) { bestd = dist; besti = c; }
    }

    float lsum = 0.0f;
    const float* cp = scb + besti * VQ_D;
    float* qp = q + (size_t)n * VQ_D * 4096 + hw;
    #pragma unroll
    for (int d = 0; d < VQ_D; d++) {
        const float cv = cp[d];
        qp[(size_t)d * 4096] = cv;
        const float df = zv[d] - cv;
        lsum = fmaf(df, df, lsum);
    }
    const float bsum = blockReduceSum(lsum);
    if (threadIdx.x == 0) atomicAdd(&g_vq_loss, (double)bsum);
}

__global__ void __launch_bounds__(256) recon_loss_kernel(
    const float* __restrict__ rec, const float* __restrict__ inp, int total)
{
    float lsum = 0.0f;
    for (int i = blockIdx.x * blockDim.x + threadIdx.x; i < total;
         i += gridDim.x * blockDim.x) {
        const float d = rec[i] - inp[i];
        lsum = fmaf(d, d, lsum);
    }
    const float bsum = blockReduceSum(lsum);
    if (threadIdx.x == 0) atomicAdd(&g_rec_loss, (double)bsum);
}

__global__ void finalize_kernel(float* out, int out_size) {
    const double recon = g_rec_loss / 3145728.0;
    const double vq = g_vq_loss / 4194304.0;
    out[out_size - 2] = (float)(recon + 1.25 * vq);
    out[out_size - 1] = (float)recon;
}

// ---------------------------------------------------------------------------
extern "C" void kernel_launch(void* const* d_in, const int* in_sizes, int n_in,
                              void* d_out, int out_size)
{
    const float* inp        = (const float*)d_in[0];
    const float* enc_w1     = (const float*)d_in[1];
    const float* enc_b1     = (const float*)d_in[2];
    const float* enc_w2     = (const float*)d_in[3];
    const float* enc_b2     = (const float*)d_in[4];
    const float* enc_w3     = (const float*)d_in[5];
    const float* enc_b3     = (const float*)d_in[6];
    const float* enc_res_w1 = (const float*)d_in[7];
    const float* enc_res_w2 = (const float*)d_in[8];
    const float* vq_w       = (const float*)d_in[9];
    const float* vq_b       = (const float*)d_in[10];
    const float* codebook   = (const float*)d_in[11];
    const float* dec_w1     = (const float*)d_in[12];
    const float* dec_b1     = (const float*)d_in[13];
    const float* dec_res_w1 = (const float*)d_in[14];
    const float* dec_res_w2 = (const float*)d_in[15];
    const float* dec_w2t    = (const float*)d_in[16];
    const float* dec_b2     = (const float*)d_in[17];
    const float* dec_w3t    = (const float*)d_in[18];
    const float* dec_b3     = (const float*)d_in[19];

    float *bufA, *bufB, *bufC, *half, *zb, *qb, *d1, *d2, *eb;
    cudaGetSymbolAddress((void**)&bufA, g_bufA);
    cudaGetSymbolAddress((void**)&bufB, g_bufB);
    cudaGetSymbolAddress((void**)&bufC, g_bufC);
    cudaGetSymbolAddress((void**)&half, g_half);
    cudaGetSymbolAddress((void**)&zb, g_z);
    cudaGetSymbolAddress((void**)&qb, g_q);
    cudaGetSymbolAddress((void**)&d1, g_d1);
    cudaGetSymbolAddress((void**)&d2, g_d2);
    cudaGetSymbolAddress((void**)&eb, g_e);

    cudaFuncSetAttribute(vq_kernel, cudaFuncAttributeMaxDynamicSharedMemorySize,
                         VQ_SMEM);
    cudaFuncSetAttribute(conv4x4s2_tiled,
                         cudaFuncAttributeMaxDynamicSharedMemorySize, K4_SMEM);
    cudaFuncSetAttribute(conv3x3_big<false, true>,
                         cudaFuncAttributeMaxDynamicSharedMemorySize, C3_SMEM);
    cudaFuncSetAttribute(conv3x3_big<true, false>,
                         cudaFuncAttributeMaxDynamicSharedMemorySize, C3_SMEM);
    cudaFuncSetAttribute(conv3x3_mma<2, false, true>,
                         cudaFuncAttributeMaxDynamicSharedMemorySize,
                         C3MMA_SMEM(2));
    cudaFuncSetAttribute(conv3x3_mma<1, true, false>,
                         cudaFuncAttributeMaxDynamicSharedMemorySize,
                         C3MMA_SMEM(1));

    zero_losses_kernel<<<1, 1>>>();

    // ---- Encoder (all fp32 — exact z, no VQ flips) ----
    conv4x4s2_tiled<<<dim3(16, 8, NB), 256, K4_SMEM>>>(
        inp, enc_w1, enc_b1, bufA, 3, 256, 256, 64, 128, 128);
    conv4x4s2_tiled<<<dim3(4, 16, NB), 256, K4_SMEM>>>(
        bufA, enc_w2, enc_b2, bufB, 64, 128, 128, 128, 64, 64);
    conv3x3_big<false, true><<<dim3(2, 16, NB), 256, C3_SMEM>>>(
        bufB, enc_w3, enc_b3, bufC, 128, 128);

    {
        float* cur = bufC;
        float* alt = bufB;
        for (int i = 0; i < 3; i++) {
            conv3x3_big<true, false><<<dim3(2, 8, NB), 256, C3_SMEM>>>(
                cur, enc_res_w1 + (size_t)i * 64 * 128 * 9, nullptr, half,
                128, 64);
            conv1x1_k<true, false, true><<<dim3(4, 16, NB), 256>>>(
                half, enc_res_w2 + (size_t)i * 128 * 64, nullptr, cur, alt,
                64, 128);
            float* t = cur; cur = alt; alt = t;
        }
        conv1x1_k<false, true, false><<<dim3(4, 8, NB), 256>>>(
            cur, vq_w, vq_b, nullptr, zb, 128, 64);
    }

    // ---- VQ ----
    vq_kernel<<<256, 256, VQ_SMEM>>>(zb, codebook, qb);

    // ---- Decoder (3x3 via 3xTF32 mma — diagnostic deployment) ----
    conv3x3_mma<2, false, true><<<dim3(16, 1, NB), 256, C3MMA_SMEM(2)>>>(
        qb, dec_w1, dec_b1, d1, 64, 64);
    {
        float* cur = d1;
        float* alt = d2;
        for (int i = 0; i < 3; i++) {
            conv3x3_mma<1, true, false><<<dim3(8, 1, NB), 256, C3MMA_SMEM(1)>>>(
                cur, dec_res_w1 + (size_t)i * 32 * 64 * 9, nullptr, half,
                64, 32);
            conv1x1_k<true, false, true><<<dim3(4, 8, NB), 256>>>(
                half, dec_res_w2 + (size_t)i * 64 * 32, nullptr, cur, alt,
                32, 64);
            float* t = cur; cur = alt; alt = t;
        }
        deconv4x4s2_tiled<4><<<dim3(8, 8, NB), 256>>>(
            cur, dec_w2t, dec_b2, eb, 64, 64, 64, 32);
    }
    deconv4x4s2_tiled<3><<<dim3(32, 1, NB), 256>>>(
        eb, dec_w3t, dec_b3, (float*)d_out, 32, 128, 128, 3);

    // ---- Losses ----
    recon_loss_kernel<<<1024, 256>>>((const float*)d_out, inp, 3145728);
    finalize_kernel<<<1, 1>>>((float*)d_out, out_size);
}

// round 10
// speedup vs baseline: 1.1280x; 1.1280x over previous
#include <cuda_runtime.h>
#include <cstdint>

// ---------------------------------------------------------------------------
// VQ-VAE forward, sm_100a. Round 9: R8 with the conv4x4s2_big halo-staging
// bug fixed (264 halo elements > 256 threads -> strided loop).
// ---------------------------------------------------------------------------

#define NB 16

__device__ float g_bufA[(size_t)NB * 64 * 128 * 128];
__device__ float g_bufB[(size_t)NB * 128 * 64 * 64];
__device__ float g_bufC[(size_t)NB * 128 * 64 * 64];
__device__ float g_half[(size_t)NB * 64 * 64 * 64];
__device__ float g_z[(size_t)NB * 64 * 64 * 64];
__device__ float g_q[(size_t)NB * 64 * 64 * 64];
__device__ float g_d1[(size_t)NB * 64 * 64 * 64];
__device__ float g_d2[(size_t)NB * 64 * 64 * 64];
__device__ float g_e[(size_t)NB * 32 * 128 * 128];
__device__ double g_vq_loss;
__device__ double g_rec_loss;

__global__ void zero_losses_kernel() {
    g_vq_loss = 0.0;
    g_rec_loss = 0.0;
}

// ---------------------------------------------------------------------------
// fp32 big-tile 3x3 conv (proven). Block 256 (16x16).
// Block tile: 32 rows x 64 cols x 8 co. Thread: 2x4 out x 8 co.
// grid = (2, Co/8, N)
// ---------------------------------------------------------------------------
#define C3_SMEM ((8 * 34 * 68 + 8 * 8 * 12) * 4)

template <bool RELU, bool BIAS>
__global__ void __launch_bounds__(256, 2) conv3x3_big(
    const float* __restrict__ in, const float* __restrict__ w,
    const float* __restrict__ bias, float* __restrict__ out,
    int Ci, int Co)
{
    extern __shared__ float sm[];
    float (*sIn)[34][68] = reinterpret_cast<float(*)[34][68]>(sm);
    float (*sW)[8][12] = reinterpret_cast<float(*)[8][12]>(sm + 8 * 34 * 68);

    const int n = blockIdx.z;
    const int cog = blockIdx.y;
    const int oh0 = blockIdx.x * 32;
    const int t = threadIdx.x;
    const int tx = t & 15, ty = t >> 4;

    if (t < 34) {
        #pragma unroll
        for (int ci = 0; ci < 8; ci++) {
            sIn[ci][t][0] = 0.0f;
            sIn[ci][t][65] = 0.0f;
        }
    }

    float acc[8][8];
    #pragma unroll
    for (int i = 0; i < 8; i++)
        #pragma unroll
        for (int j = 0; j < 8; j++) acc[i][j] = 0.0f;

    const float* inb = in + (size_t)n * Ci * 4096;
    const int c64 = t & 63;
    const int r4 = t >> 6;

    for (int cb = 0; cb < Ci; cb += 8) {
        __syncthreads();
        #pragma unroll
        for (int ci = 0; ci < 8; ci++) {
            const float* g = inb + (size_t)(cb + ci) * 4096 + c64;
            #pragma unroll
            for (int rb = 0; rb < 36; rb += 4) {
                const int r = rb + r4;
                if (r < 34) {
                    const int ih = oh0 - 1 + r;
                    float v = 0.0f;
                    if (ih >= 0 && ih < 64) v = g[ih * 64];
                    sIn[ci][r][c64 + 1] = v;
                }
            }
        }
        for (int i = t; i < 576; i += 256) {
            const int co = i / 72;
            const int rem = i - co * 72;
            const int ci = rem / 9;
            const int k = rem - ci * 9;
            sW[co][ci][k] = w[(((size_t)(cog * 8 + co)) * Ci + cb + ci) * 9 + k];
        }
        __syncthreads();

        #pragma unroll 1
        for (int ci = 0; ci < 8; ci++) {
            float iv[4][6];
            #pragma unroll
            for (int r = 0; r < 4; r++) {
                const float* rp = &sIn[ci][2 * ty + r][4 * tx];
                const float4 a = *reinterpret_cast<const float4*>(rp);
                const float2 b = *reinterpret_cast<const float2*>(rp + 4);
                iv[r][0] = a.x; iv[r][1] = a.y; iv[r][2] = a.z;
                iv[r][3] = a.w; iv[r][4] = b.x; iv[r][5] = b.y;
            }
            #pragma unroll
            for (int co = 0; co < 8; co++) {
                const float4* wq = reinterpret_cast<const float4*>(&sW[co][ci][0]);
                const float4 w0 = wq[0], w1 = wq[1];
                const float w8 = sW[co][ci][8];
                const float wv[9] = {w0.x, w0.y, w0.z, w0.w,
                                     w1.x, w1.y, w1.z, w1.w, w8};
                #pragma unroll
                for (int r2 = 0; r2 < 2; r2++)
                    #pragma unroll
                    for (int c2 = 0; c2 < 4; c2++) {
                        float a = acc[co][r2 * 4 + c2];
                        #pragma unroll
                        for (int kh = 0; kh < 3; kh++)
                            #pragma unroll
                            for (int kw = 0; kw < 3; kw++)
                                a = fmaf(iv[r2 + kh][c2 + kw],
                                         wv[kh * 3 + kw], a);
                        acc[co][r2 * 4 + c2] = a;
                    }
            }
        }
    }

    float* outb = out + ((size_t)n * Co + cog * 8) * 4096;
    #pragma unroll
    for (int co = 0; co < 8; co++) {
        const float b = BIAS ? bias[cog * 8 + co] : 0.0f;
        #pragma unroll
        for (int r2 = 0; r2 < 2; r2++) {
            const int oh = oh0 + 2 * ty + r2;
            float4 v = make_float4(acc[co][r2 * 4 + 0] + b,
                                   acc[co][r2 * 4 + 1] + b,
                                   acc[co][r2 * 4 + 2] + b,
                                   acc[co][r2 * 4 + 3] + b);
            if (RELU) {
                v.x = fmaxf(v.x, 0.f); v.y = fmaxf(v.y, 0.f);
                v.z = fmaxf(v.z, 0.f); v.w = fmaxf(v.w, 0.f);
            }
            *reinterpret_cast<float4*>(
                outb + (size_t)co * 4096 + oh * 64 + 4 * tx) = v;
        }
    }
}

// ---------------------------------------------------------------------------
// Big-tile 4x4 stride-2 pad-1 conv. Block 256 (16x16).
// Block tile: 32 out-rows x 64 out-cols x 8 co. Thread: 2x4 out x 8 co.
// smem: sIn[2][66][132] (input rows 2*oh0-1..+64, cols 2*ow0-1..+130 at +1),
// sW[2][8][16]. Div-free core staging (cols via t&127); halo via strided
// loop over all 264 elements (FIX: was `if (t < 264)` with 256 threads).
// grid = ((Ho/32)*(Wo/64), Co/8, N); ntx = Wo/64.
// ---------------------------------------------------------------------------
#define K4B_SMEM ((2 * 66 * 132 + 2 * 8 * 16) * 4)

__global__ void __launch_bounds__(256, 2) conv4x4s2_big(
    const float* __restrict__ in, const float* __restrict__ w,
    const float* __restrict__ bias, float* __restrict__ out,
    int Ci, int Hi, int Wi, int Co, int ntx)
{
    extern __shared__ float sm[];
    float (*sIn)[66][132] = reinterpret_cast<float(*)[66][132]>(sm);
    float (*sW)[8][16] =
        reinterpret_cast<float(*)[8][16]>(sm + 2 * 66 * 132);

    const int Ho = Hi >> 1, Wo = Wi >> 1;
    const int n = blockIdx.z;
    const int cog = blockIdx.y;
    const int tileY = blockIdx.x / ntx;
    const int tileX = blockIdx.x - tileY * ntx;
    const int oh0 = tileY * 32, ow0 = tileX * 64;
    const int t = threadIdx.x;
    const int tx = t & 15, ty = t >> 4;

    float acc[8][8];
    #pragma unroll
    for (int i = 0; i < 8; i++)
        #pragma unroll
        for (int j = 0; j < 8; j++) acc[i][j] = 0.0f;

    const float* inb = in + (size_t)n * Ci * Hi * Wi;
    const int c128 = t & 127;
    const int rphase = t >> 7;   // 0..1

    for (int cb = 0; cb < Ci; cb += 2) {
        __syncthreads();
        // core staging: smem cols 1..128 <- global cols 2*ow0 + c128
        #pragma unroll
        for (int ci = 0; ci < 2; ci++) {
            const int cig = cb + ci;
            const bool cok = (cig < Ci);
            const float* g = inb + (size_t)cig * Hi * Wi + 2 * ow0 + c128;
            #pragma unroll
            for (int rb = 0; rb < 66; rb += 2) {
                const int r = rb + rphase;
                const int ih = 2 * oh0 - 1 + r;
                float v = 0.0f;
                if (cok && ih >= 0 && ih < Hi) v = g[(size_t)ih * Wi];
                sIn[ci][r][c128 + 1] = v;
            }
        }
        // halo cols 0 and 129: 2 ci x 2 sides x 66 rows = 264 elements
        for (int i = t; i < 264; i += 256) {
            const int ci = i / 132;
            const int rem = i - ci * 132;
            const int side = rem / 66;         // 0 -> col 0, 1 -> col 129
            const int r = rem - side * 66;
            const int ih = 2 * oh0 - 1 + r;
            const int gw = side ? (2 * ow0 + 128) : (2 * ow0 - 1);
            const int cig = cb + ci;
            float v = 0.0f;
            if (cig < Ci && ih >= 0 && ih < Hi && gw >= 0 && gw < Wi)
                v = inb[(size_t)cig * Hi * Wi + (size_t)ih * Wi + gw];
            sIn[ci][r][side ? 129 : 0] = v;
        }
        // weights: 2 ci x 8 co x 16
        {
            const int ci = t >> 7;
            const int co = (t >> 4) & 7;
            const int k = t & 15;
            const int cig = cb + ci;
            sW[ci][co][k] = (cig < Ci)
                ? w[(((size_t)(cog * 8 + co)) * Ci + cig) * 16 + k] : 0.0f;
        }
        __syncthreads();

        #pragma unroll
        for (int ci = 0; ci < 2; ci++) {
            #pragma unroll
            for (int kh = 0; kh < 4; kh++) {
                float iv[2][10];
                #pragma unroll
                for (int r2 = 0; r2 < 2; r2++) {
                    const float* rp = &sIn[ci][4 * ty + 2 * r2 + kh][8 * tx];
                    const float4 a = *reinterpret_cast<const float4*>(rp);
                    const float4 b = *reinterpret_cast<const float4*>(rp + 4);
                    const float2 c = *reinterpret_cast<const float2*>(rp + 8);
                    iv[r2][0] = a.x; iv[r2][1] = a.y; iv[r2][2] = a.z;
                    iv[r2][3] = a.w; iv[r2][4] = b.x; iv[r2][5] = b.y;
                    iv[r2][6] = b.z; iv[r2][7] = b.w; iv[r2][8] = c.x;
                    iv[r2][9] = c.y;
                }
                #pragma unroll
                for (int co = 0; co < 8; co++) {
                    const float4 wq = *reinterpret_cast<const float4*>(
                        &sW[ci][co][kh * 4]);
                    const float wv[4] = {wq.x, wq.y, wq.z, wq.w};
                    #pragma unroll
                    for (int r2 = 0; r2 < 2; r2++)
                        #pragma unroll
                        for (int c2 = 0; c2 < 4; c2++) {
                            float a = acc[co][r2 * 4 + c2];
                            #pragma unroll
                            for (int kw = 0; kw < 4; kw++)
                                a = fmaf(iv[r2][2 * c2 + kw], wv[kw], a);
                            acc[co][r2 * 4 + c2] = a;
                        }
                }
            }
        }
    }

    #pragma unroll
    for (int co = 0; co < 8; co++) {
        const float b = bias[cog * 8 + co];
        float* ob = out + ((size_t)n * Co + cog * 8 + co) * Ho * Wo;
        #pragma unroll
        for (int r2 = 0; r2 < 2; r2++) {
            const int oh = oh0 + 2 * ty + r2;
            const float4 v = make_float4(acc[co][r2 * 4 + 0] + b,
                                         acc[co][r2 * 4 + 1] + b,
                                         acc[co][r2 * 4 + 2] + b,
                                         acc[co][r2 * 4 + 3] + b);
            *reinterpret_cast<float4*>(
                ob + (size_t)oh * Wo + ow0 + 4 * tx) = v;
        }
    }
}

// ---------------------------------------------------------------------------
// 1x1 conv (fp32).
// ---------------------------------------------------------------------------
template <bool RELU, bool BIAS, bool RES>
__global__ void __launch_bounds__(256) conv1x1_k(
    const float* __restrict__ in, const float* __restrict__ w,
    const float* __restrict__ bias, const float* __restrict__ res,
    float* __restrict__ out, int Ci, int Co)
{
    __shared__ float sW1[8 * 128];
    const int n = blockIdx.z;
    const int cog = blockIdx.y;
    const int hw = blockIdx.x * 1024 + threadIdx.x * 4;
    const int t = threadIdx.x;

    for (int i = t; i < 8 * Ci; i += 256)
        sW1[i] = w[(size_t)cog * 8 * Ci + i];
    __syncthreads();

    const float* ip = in + (size_t)n * Ci * 4096 + hw;
    float4 acc[8];
    #pragma unroll
    for (int co = 0; co < 8; co++) acc[co] = make_float4(0.f, 0.f, 0.f, 0.f);

    #pragma unroll 2
    for (int ci = 0; ci < Ci; ci++) {
        const float4 xv = *reinterpret_cast<const float4*>(ip + (size_t)ci * 4096);
        #pragma unroll
        for (int co = 0; co < 8; co++) {
            const float wv = sW1[co * Ci + ci];
            acc[co].x = fmaf(xv.x, wv, acc[co].x);
            acc[co].y = fmaf(xv.y, wv, acc[co].y);
            acc[co].z = fmaf(xv.z, wv, acc[co].z);
            acc[co].w = fmaf(xv.w, wv, acc[co].w);
        }
    }

    #pragma unroll
    for (int co = 0; co < 8; co++) {
        float4 v = acc[co];
        if (BIAS) {
            const float b = bias[cog * 8 + co];
            v.x += b; v.y += b; v.z += b; v.w += b;
        }
        if (RELU) {
            v.x = fmaxf(v.x, 0.f); v.y = fmaxf(v.y, 0.f);
            v.z = fmaxf(v.z, 0.f); v.w = fmaxf(v.w, 0.f);
        }
        const size_t o = ((size_t)n * Co + cog * 8 + co) * 4096 + hw;
        if (RES) {
            const float4 r = *reinterpret_cast<const float4*>(res + o);
            v.x += r.x; v.y += r.y; v.z += r.z; v.w += r.w;
        }
        *reinterpret_cast<float4*>(out + o) = v;
    }
}

// ---------------------------------------------------------------------------
// Transposed conv k4 s2 p1 (fp32).
// ---------------------------------------------------------------------------
template <int CO_T>
__global__ void __launch_bounds__(256) deconv4x4s2_tiled(
    const float* __restrict__ in, const float* __restrict__ w,
    const float* __restrict__ bias, float* __restrict__ out,
    int Ci, int Hi, int Wi, int Co)
{
    __shared__ float sIn[8][18][36];
    __shared__ float sW[8 * CO_T * 16];

    const int n = blockIdx.z;
    const int cog = blockIdx.y;
    const int ntx = Wi >> 5;
    const int tileY = blockIdx.x / ntx;
    const int tileX = blockIdx.x - tileY * ntx;
    const int i0 = tileY * 16, j0 = tileX * 32;
    const int t = threadIdx.x;
    const int tx = t & 15, ty = t >> 4;

    float acc[CO_T][2][4];
    #pragma unroll
    for (int c = 0; c < CO_T; c++)
        #pragma unroll
        for (int a = 0; a < 2; a++)
            #pragma unroll
            for (int j = 0; j < 4; j++) acc[c][a][j] = 0.0f;

    const float* inb = in + (size_t)n * Ci * Hi * Wi;

    const int RR[2][2] = {{1, 0}, {2, 1}};
    const int KH[2][2] = {{1, 3}, {0, 2}};
    const int CC[2][2] = {{1, 0}, {2, 1}};
    const int KW[2][2] = {{1, 3}, {0, 2}};

    for (int cb = 0; cb < Ci; cb += 8) {
        __syncthreads();
        for (int i = t; i < 8 * 18 * 34; i += 256) {
            const int ci = i / 612;
            const int rem = i - ci * 612;
            const int r = rem / 34;
            const int c = rem - r * 34;
            const int ih = i0 - 1 + r;
            const int iw = j0 - 1 + c;
            float v = 0.0f;
            if (ih >= 0 && ih < Hi && iw >= 0 && iw < Wi)
                v = inb[(size_t)(cb + ci) * Hi * Wi + ih * Wi + iw];
            sIn[ci][r][c] = v;
        }
        for (int i = t; i < 8 * CO_T * 16; i += 256) {
            const int ci = i / (CO_T * 16);
            const int rem = i - ci * (CO_T * 16);
            const int co = rem >> 4;
            const int k = rem & 15;
            sW[i] = w[(((size_t)(cb + ci)) * Co + cog * CO_T + co) * 16 + k];
        }
        __syncthreads();

        #pragma unroll 1
        for (int ci = 0; ci < 8; ci++) {
            float iv[3][4];
            #pragma unroll
            for (int r = 0; r < 3; r++) {
                const float2* rp = reinterpret_cast<const float2*>(
                    &sIn[ci][ty + r][2 * tx]);
                const float2 a = rp[0], b = rp[1];
                iv[r][0] = a.x; iv[r][1] = a.y; iv[r][2] = b.x; iv[r][3] = b.y;
            }
            #pragma unroll
            for (int co = 0; co < CO_T; co++) {
                const float4* wq = reinterpret_cast<const float4*>(
                    sW + (ci * CO_T + co) * 16);
                const float4 q0 = wq[0], q1 = wq[1], q2 = wq[2], q3 = wq[3];
                float wv[16] = {q0.x, q0.y, q0.z, q0.w, q1.x, q1.y, q1.z, q1.w,
                                q2.x, q2.y, q2.z, q2.w, q3.x, q3.y, q3.z, q3.w};
                #pragma unroll
                for (int q = 0; q < 2; q++)
                    #pragma unroll
                    for (int a = 0; a < 2; a++)
                        #pragma unroll
                        for (int b = 0; b < 2; b++) {
                            float s = acc[co][a][2 * q + b];
                            #pragma unroll
                            for (int si = 0; si < 2; si++)
                                #pragma unroll
                                for (int ti = 0; ti < 2; ti++)
                                    s = fmaf(iv[RR[a][si]][q + CC[b][ti]],
                                             wv[KH[a][si] * 4 + KW[b][ti]], s);
                            acc[co][a][2 * q + b] = s;
                        }
            }
        }
    }

    const int Ho = 2 * Hi, Wo = 2 * Wi;
    const int ow = 2 * j0 + 4 * tx;
    #pragma unroll
    for (int co = 0; co < CO_T; co++) {
        const float b = bias[cog * CO_T + co];
        float* ob = out + ((size_t)n * Co + cog * CO_T + co) * Ho * Wo;
        #pragma unroll
        for (int a = 0; a < 2; a++) {
            const int oh = 2 * (i0 + ty) + a;
            *reinterpret_cast<float4*>(ob + (size_t)oh * Wo + ow) =
                make_float4(acc[co][a][0] + b, acc[co][a][1] + b,
                            acc[co][a][2] + b, acc[co][a][3] + b);
        }
    }
}

// ---------------------------------------------------------------------------
__device__ __forceinline__ float blockReduceSum(float v) {
    __shared__ float sh[32];
    #pragma unroll
    for (int o = 16; o > 0; o >>= 1) v += __shfl_down_sync(0xffffffffu, v, o);
    if ((threadIdx.x & 31) == 0) sh[threadIdx.x >> 5] = v;
    __syncthreads();
    const int nw = (blockDim.x + 31) >> 5;
    v = (threadIdx.x < (unsigned)nw) ? sh[threadIdx.x] : 0.0f;
    if (threadIdx.x < 32) {
        #pragma unroll
        for (int o = 16; o > 0; o >>= 1) v += __shfl_down_sync(0xffffffffu, v, o);
    }
    return v;
}

#define VQ_K 512
#define VQ_D 64
#define VQ_SMEM ((VQ_K * VQ_D + VQ_K) * 4)

__global__ void __launch_bounds__(256) vq_kernel(
    const float* __restrict__ z, const float* __restrict__ cb,
    float* __restrict__ q)
{
    extern __shared__ float smem[];
    float* scb = smem;
    float* snorm = smem + VQ_K * VQ_D;

    for (int i = threadIdx.x; i < VQ_K * VQ_D; i += blockDim.x)
        scb[i] = cb[i];
    __syncthreads();
    for (int c = threadIdx.x; c < VQ_K; c += blockDim.x) {
        float s = 0.0f;
        const float* cp = scb + c * VQ_D;
        #pragma unroll 16
        for (int d = 0; d < VQ_D; d++) s = fmaf(cp[d], cp[d], s);
        snorm[c] = s;
    }
    __syncthreads();

    const int pos = blockIdx.x * blockDim.x + threadIdx.x;
    const int n = pos >> 12;
    const int hw = pos & 4095;

    float zv[VQ_D];
    const float* zp = z + (size_t)n * VQ_D * 4096 + hw;
    float zn = 0.0f;
    #pragma unroll
    for (int d = 0; d < VQ_D; d++) {
        zv[d] = zp[(size_t)d * 4096];
        zn = fmaf(zv[d], zv[d], zn);
    }

    float bestd = 3.402823466e+38f;
    int besti = 0;
    for (int c = 0; c < VQ_K; c++) {
        const float4* cp4 = reinterpret_cast<const float4*>(scb + c * VQ_D);
        float dot = 0.0f;
        #pragma unroll
        for (int d4 = 0; d4 < VQ_D / 4; d4++) {
            const float4 cv = cp4[d4];
            dot = fmaf(zv[4 * d4 + 0], cv.x, dot);
            dot = fmaf(zv[4 * d4 + 1], cv.y, dot);
            dot = fmaf(zv[4 * d4 + 2], cv.z, dot);
            dot = fmaf(zv[4 * d4 + 3], cv.w, dot);
        }
        const float dist = zn - 2.0f * dot + snorm[c];
        if (dist < bestd) { bestd = dist; besti = c; }
    }

    float lsum = 0.0f;
    const float* cp = scb + besti * VQ_D;
    float* qp = q + (size_t)n * VQ_D * 4096 + hw;
    #pragma unroll
    for (int d = 0; d < VQ_D; d++) {
        const float cv = cp[d];
        qp[(size_t)d * 4096] = cv;
        const float df = zv[d] - cv;
        lsum = fmaf(df, df, lsum);
    }
    const float bsum = blockReduceSum(lsum);
    if (threadIdx.x == 0) atomicAdd(&g_vq_loss, (double)bsum);
}

__global__ void __launch_bounds__(256) recon_loss_kernel(
    const float* __restrict__ rec, const float* __restrict__ inp, int total)
{
    float lsum = 0.0f;
    for (int i = blockIdx.x * blockDim.x + threadIdx.x; i < total;
         i += gridDim.x * blockDim.x) {
        const float d = rec[i] - inp[i];
        lsum = fmaf(d, d, lsum);
    }
    const float bsum = blockReduceSum(lsum);
    if (threadIdx.x == 0) atomicAdd(&g_rec_loss, (double)bsum);
}

__global__ void finalize_kernel(float* out, int out_size) {
    const double recon = g_rec_loss / 3145728.0;
    const double vq = g_vq_loss / 4194304.0;
    out[out_size - 2] = (float)(recon + 1.25 * vq);
    out[out_size - 1] = (float)recon;
}

// ---------------------------------------------------------------------------
extern "C" void kernel_launch(void* const* d_in, const int* in_sizes, int n_in,
                              void* d_out, int out_size)
{
    const float* inp        = (const float*)d_in[0];
    const float* enc_w1     = (const float*)d_in[1];
    const float* enc_b1     = (const float*)d_in[2];
    const float* enc_w2     = (const float*)d_in[3];
    const float* enc_b2     = (const float*)d_in[4];
    const float* enc_w3     = (const float*)d_in[5];
    const float* enc_b3     = (const float*)d_in[6];
    const float* enc_res_w1 = (const float*)d_in[7];
    const float* enc_res_w2 = (const float*)d_in[8];
    const float* vq_w       = (const float*)d_in[9];
    const float* vq_b       = (const float*)d_in[10];
    const float* codebook   = (const float*)d_in[11];
    const float* dec_w1     = (const float*)d_in[12];
    const float* dec_b1     = (const float*)d_in[13];
    const float* dec_res_w1 = (const float*)d_in[14];
    const float* dec_res_w2 = (const float*)d_in[15];
    const float* dec_w2t    = (const float*)d_in[16];
    const float* dec_b2     = (const float*)d_in[17];
    const float* dec_w3t    = (const float*)d_in[18];
    const float* dec_b3     = (const float*)d_in[19];

    float *bufA, *bufB, *bufC, *half, *zb, *qb, *d1, *d2, *eb;
    cudaGetSymbolAddress((void**)&bufA, g_bufA);
    cudaGetSymbolAddress((void**)&bufB, g_bufB);
    cudaGetSymbolAddress((void**)&bufC, g_bufC);
    cudaGetSymbolAddress((void**)&half, g_half);
    cudaGetSymbolAddress((void**)&zb, g_z);
    cudaGetSymbolAddress((void**)&qb, g_q);
    cudaGetSymbolAddress((void**)&d1, g_d1);
    cudaGetSymbolAddress((void**)&d2, g_d2);
    cudaGetSymbolAddress((void**)&eb, g_e);

    cudaFuncSetAttribute(vq_kernel, cudaFuncAttributeMaxDynamicSharedMemorySize,
                         VQ_SMEM);
    cudaFuncSetAttribute(conv4x4s2_big,
                         cudaFuncAttributeMaxDynamicSharedMemorySize, K4B_SMEM);
    cudaFuncSetAttribute(conv3x3_big<false, true>,
                         cudaFuncAttributeMaxDynamicSharedMemorySize, C3_SMEM);
    cudaFuncSetAttribute(conv3x3_big<true, false>,
                         cudaFuncAttributeMaxDynamicSharedMemorySize, C3_SMEM);

    zero_losses_kernel<<<1, 1>>>();

    // ---- Encoder ----
    // enc1: 3->64, 256->128. grid = ((128/32)*(128/64), 64/8, N), ntx=2
    conv4x4s2_big<<<dim3(8, 8, NB), 256, K4B_SMEM>>>(
        inp, enc_w1, enc_b1, bufA, 3, 256, 256, 64, 2);
    // enc2: 64->128, 128->64. grid = ((64/32)*(64/64), 128/8, N), ntx=1
    conv4x4s2_big<<<dim3(2, 16, NB), 256, K4B_SMEM>>>(
        bufA, enc_w2, enc_b2, bufB, 64, 128, 128, 128, 1);
    // enc3: 128->128, 3x3
    conv3x3_big<false, true><<<dim3(2, 16, NB), 256, C3_SMEM>>>(
        bufB, enc_w3, enc_b3, bufC, 128, 128);

    {
        float* cur = bufC;
        float* alt = bufB;
        for (int i = 0; i < 3; i++) {
            conv3x3_big<true, false><<<dim3(2, 8, NB), 256, C3_SMEM>>>(
                cur, enc_res_w1 + (size_t)i * 64 * 128 * 9, nullptr, half,
                128, 64);
            conv1x1_k<true, false, true><<<dim3(4, 16, NB), 256>>>(
                half, enc_res_w2 + (size_t)i * 128 * 64, nullptr, cur, alt,
                64, 128);
            float* t = cur; cur = alt; alt = t;
        }
        conv1x1_k<false, true, false><<<dim3(4, 8, NB), 256>>>(
            cur, vq_w, vq_b, nullptr, zb, 128, 64);
    }

    // ---- VQ ----
    vq_kernel<<<256, 256, VQ_SMEM>>>(zb, codebook, qb);

    // ---- Decoder (all fp32, proven) ----
    conv3x3_big<false, true><<<dim3(2, 8, NB), 256, C3_SMEM>>>(
        qb, dec_w1, dec_b1, d1, 64, 64);
    {
        float* cur = d1;
        float* alt = d2;
        for (int i = 0; i < 3; i++) {
            conv3x3_big<true, false><<<dim3(2, 4, NB), 256, C3_SMEM>>>(
                cur, dec_res_w1 + (size_t)i * 32 * 64 * 9, nullptr, half,
                64, 32);
            conv1x1_k<true, false, true><<<dim3(4, 8, NB), 256>>>(
                half, dec_res_w2 + (size_t)i * 64 * 32, nullptr, cur, alt,
                32, 64);
            float* t = cur; cur = alt; alt = t;
        }
        deconv4x4s2_tiled<4><<<dim3(8, 8, NB), 256>>>(
            cur, dec_w2t, dec_b2, eb, 64, 64, 64, 32);
    }
    deconv4x4s2_tiled<3><<<dim3(32, 1, NB), 256>>>(
        eb, dec_w3t, dec_b3, (float*)d_out, 32, 128, 128, 3);

    // ---- Losses ----
    recon_loss_kernel<<<1024, 256>>>((const float*)d_out, inp, 3145728);
    finalize_kernel<<<1, 1>>>((float*)d_out, out_size);
}

// round 11
// speedup vs baseline: 1.2328x; 1.0929x over previous
#include <cuda_runtime.h>
#include <cstdint>

// ---------------------------------------------------------------------------
// VQ-VAE forward, sm_100a. Round 10: 3x3 convs get cp.async 2-stage double
// buffering (conv3x3_pipe). Everything else identical to round 9.
// ---------------------------------------------------------------------------

#define NB 16

__device__ float g_bufA[(size_t)NB * 64 * 128 * 128];
__device__ float g_bufB[(size_t)NB * 128 * 64 * 64];
__device__ float g_bufC[(size_t)NB * 128 * 64 * 64];
__device__ float g_half[(size_t)NB * 64 * 64 * 64];
__device__ float g_z[(size_t)NB * 64 * 64 * 64];
__device__ float g_q[(size_t)NB * 64 * 64 * 64];
__device__ float g_d1[(size_t)NB * 64 * 64 * 64];
__device__ float g_d2[(size_t)NB * 64 * 64 * 64];
__device__ float g_e[(size_t)NB * 32 * 128 * 128];
__device__ double g_vq_loss;
__device__ double g_rec_loss;

__global__ void zero_losses_kernel() {
    g_vq_loss = 0.0;
    g_rec_loss = 0.0;
}

// ---------------------------------------------------------------------------
// cp.async helpers
// ---------------------------------------------------------------------------
__device__ __forceinline__ void cp_async16(uint32_t dst, const void* src,
                                           int src_size) {
    asm volatile("cp.async.ca.shared.global [%0], [%1], 16, %2;"
                 :: "r"(dst), "l"(src), "r"(src_size));
}
__device__ __forceinline__ void cp_async4(uint32_t dst, const void* src) {
    asm volatile("cp.async.ca.shared.global [%0], [%1], 4;"
                 :: "r"(dst), "l"(src));
}
__device__ __forceinline__ void cp_commit() {
    asm volatile("cp.async.commit_group;");
}
template <int N>
__device__ __forceinline__ void cp_wait() {
    asm volatile("cp.async.wait_group %0;" :: "n"(N));
}

// ---------------------------------------------------------------------------
// 3x3 conv s1 p1, H=W=64, cp.async double-buffered. Block 256 (16x16).
// Block tile: 32 rows x 64 cols x 8 co. Thread: 2x4 out x 8 co.
// smem: sIn[2][4][34][68] — data at cols 0..63 (16B aligned for cp.async),
// cols 64..67 permanently zero (right halo + left-halo slot at col 66).
// Row OOB handled by cp.async zfill (src_size=0). sW[2][8][4][12].
// Chunks of 4 ci; stage chunk c+1 while computing chunk c.
// grid = (2, Co/8, N)
// ---------------------------------------------------------------------------
#define C3P_SMEM ((2 * 4 * 34 * 68 + 2 * 8 * 4 * 12) * 4)

template <bool RELU, bool BIAS>
__global__ void __launch_bounds__(256, 2) conv3x3_pipe(
    const float* __restrict__ in, const float* __restrict__ w,
    const float* __restrict__ bias, float* __restrict__ out,
    int Ci, int Co)
{
    extern __shared__ float sm[];
    float* sInBase = sm;                      // [ (s*4+ci)*34 + r ][68]
    float* sWBase = sm + 2 * 4 * 34 * 68;     // [ ((s*8+co)*4+ci) ][12]

    const int n = blockIdx.z;
    const int cog = blockIdx.y;
    const int oh0 = blockIdx.x * 32;
    const int t = threadIdx.x;
    const int tx = t & 15, ty = t >> 4;
    const int c16 = t & 15, rr = t >> 4;      // staging decomposition

    // zero pad cols 64..67 of all 272 rows (both stages) — written once
    for (int i = t; i < 2 * 4 * 34; i += 256) {
        float* row = sInBase + i * 68;
        row[64] = 0.f; row[65] = 0.f; row[66] = 0.f; row[67] = 0.f;
    }

    float acc[8][8];
    #pragma unroll
    for (int i = 0; i < 8; i++)
        #pragma unroll
        for (int j = 0; j < 8; j++) acc[i][j] = 0.0f;

    const float* inb = in + (size_t)n * Ci * 4096;
    const float* wb = w + (size_t)cog * 8 * Ci * 9;

    // ---- staging (all 256 threads; coverage: 4ci x 34r x 16x16B) ----
    auto stage_chunk = [&](int chunk, int s) {
        const int cbase = chunk * 4;
        #pragma unroll
        for (int ci = 0; ci < 4; ci++) {
            const float* g = inb + (size_t)(cbase + ci) * 4096;
            float* srow0 = sInBase + (size_t)((s * 4 + ci) * 34) * 68;
            #pragma unroll
            for (int p = 0; p < 3; p++) {
                const int r = rr + p * 16;
                if (r < 34) {
                    const int ih = oh0 - 1 + r;
                    const bool ok = (ih >= 0 && ih < 64);
                    const int ihc = ok ? ih : 0;   // clamp addr, zfill data
                    const uint32_t dst = (uint32_t)__cvta_generic_to_shared(
                        srow0 + r * 68 + c16 * 4);
                    cp_async16(dst, g + ihc * 64 + c16 * 4, ok ? 16 : 0);
                }
            }
        }
        // weights: 8co x 4ci x 9 = 288 scalars
        for (int i = t; i < 288; i += 256) {
            const int co = i / 36;
            const int rem = i - co * 36;
            const int ci = rem / 9;
            const int k = rem - ci * 9;
            const uint32_t dst = (uint32_t)__cvta_generic_to_shared(
                sWBase + ((s * 8 + co) * 4 + ci) * 12 + k);
            cp_async4(dst, wb + ((size_t)co * Ci + cbase + ci) * 9 + k);
        }
    };

    const int nch = Ci >> 2;
    stage_chunk(0, 0);
    cp_commit();

    for (int c = 0; c < nch; c++) {
        if (c + 1 < nch) { stage_chunk(c + 1, (c + 1) & 1); cp_commit(); }
        if (c + 1 < nch) cp_wait<1>(); else cp_wait<0>();
        __syncthreads();

        const int s = c & 1;
        #pragma unroll 1
        for (int ci = 0; ci < 4; ci++) {
            const float* rowb = sInBase + (size_t)((s * 4 + ci) * 34) * 68;
            float iv[4][6];
            #pragma unroll
            for (int r = 0; r < 4; r++) {
                const float* rp = rowb + (2 * ty + r) * 68;
                const float4 a = *reinterpret_cast<const float4*>(rp + 4 * tx);
                const float lf = (tx == 0) ? rp[66] : rp[4 * tx - 1];
                const float rg = rp[4 * tx + 4];
                iv[r][0] = lf;  iv[r][1] = a.x; iv[r][2] = a.y;
                iv[r][3] = a.z; iv[r][4] = a.w; iv[r][5] = rg;
            }
            #pragma unroll
            for (int co = 0; co < 8; co++) {
                const float* wp = sWBase + ((s * 8 + co) * 4 + ci) * 12;
                const float4 w0 = *reinterpret_cast<const float4*>(wp);
                const float4 w1 = *reinterpret_cast<const float4*>(wp + 4);
                const float w8 = wp[8];
                const float wv[9] = {w0.x, w0.y, w0.z, w0.w,
                                     w1.x, w1.y, w1.z, w1.w, w8};
                #pragma unroll
                for (int r2 = 0; r2 < 2; r2++)
                    #pragma unroll
                    for (int c2 = 0; c2 < 4; c2++) {
                        float a2 = acc[co][r2 * 4 + c2];
                        #pragma unroll
                        for (int kh = 0; kh < 3; kh++)
                            #pragma unroll
                            for (int kw = 0; kw < 3; kw++)
                                a2 = fmaf(iv[r2 + kh][c2 + kw],
                                          wv[kh * 3 + kw], a2);
                        acc[co][r2 * 4 + c2] = a2;
                    }
            }
        }
        __syncthreads();   // protect buffer s from re-staging at iter c+2
    }

    float* outb = out + ((size_t)n * Co + cog * 8) * 4096;
    #pragma unroll
    for (int co = 0; co < 8; co++) {
        const float b = BIAS ? bias[cog * 8 + co] : 0.0f;
        #pragma unroll
        for (int r2 = 0; r2 < 2; r2++) {
            const int oh = oh0 + 2 * ty + r2;
            float4 v = make_float4(acc[co][r2 * 4 + 0] + b,
                                   acc[co][r2 * 4 + 1] + b,
                                   acc[co][r2 * 4 + 2] + b,
                                   acc[co][r2 * 4 + 3] + b);
            if (RELU) {
                v.x = fmaxf(v.x, 0.f); v.y = fmaxf(v.y, 0.f);
                v.z = fmaxf(v.z, 0.f); v.w = fmaxf(v.w, 0.f);
            }
            *reinterpret_cast<float4*>(
                outb + (size_t)co * 4096 + oh * 64 + 4 * tx) = v;
        }
    }
}

// ---------------------------------------------------------------------------
// Big-tile 4x4 stride-2 pad-1 conv (R9-proven, halo fix in place).
// ---------------------------------------------------------------------------
#define K4B_SMEM ((2 * 66 * 132 + 2 * 8 * 16) * 4)

__global__ void __launch_bounds__(256, 2) conv4x4s2_big(
    const float* __restrict__ in, const float* __restrict__ w,
    const float* __restrict__ bias, float* __restrict__ out,
    int Ci, int Hi, int Wi, int Co, int ntx)
{
    extern __shared__ float sm[];
    float (*sIn)[66][132] = reinterpret_cast<float(*)[66][132]>(sm);
    float (*sW)[8][16] =
        reinterpret_cast<float(*)[8][16]>(sm + 2 * 66 * 132);

    const int Ho = Hi >> 1, Wo = Wi >> 1;
    const int n = blockIdx.z;
    const int cog = blockIdx.y;
    const int tileY = blockIdx.x / ntx;
    const int tileX = blockIdx.x - tileY * ntx;
    const int oh0 = tileY * 32, ow0 = tileX * 64;
    const int t = threadIdx.x;
    const int tx = t & 15, ty = t >> 4;

    float acc[8][8];
    #pragma unroll
    for (int i = 0; i < 8; i++)
        #pragma unroll
        for (int j = 0; j < 8; j++) acc[i][j] = 0.0f;

    const float* inb = in + (size_t)n * Ci * Hi * Wi;
    const int c128 = t & 127;
    const int rphase = t >> 7;

    for (int cb = 0; cb < Ci; cb += 2) {
        __syncthreads();
        #pragma unroll
        for (int ci = 0; ci < 2; ci++) {
            const int cig = cb + ci;
            const bool cok = (cig < Ci);
            const float* g = inb + (size_t)cig * Hi * Wi + 2 * ow0 + c128;
            #pragma unroll
            for (int rb = 0; rb < 66; rb += 2) {
                const int r = rb + rphase;
                const int ih = 2 * oh0 - 1 + r;
                float v = 0.0f;
                if (cok && ih >= 0 && ih < Hi) v = g[(size_t)ih * Wi];
                sIn[ci][r][c128 + 1] = v;
            }
        }
        for (int i = t; i < 264; i += 256) {
            const int ci = i / 132;
            const int rem = i - ci * 132;
            const int side = rem / 66;
            const int r = rem - side * 66;
            const int ih = 2 * oh0 - 1 + r;
            const int gw = side ? (2 * ow0 + 128) : (2 * ow0 - 1);
            const int cig = cb + ci;
            float v = 0.0f;
            if (cig < Ci && ih >= 0 && ih < Hi && gw >= 0 && gw < Wi)
                v = inb[(size_t)cig * Hi * Wi + (size_t)ih * Wi + gw];
            sIn[ci][r][side ? 129 : 0] = v;
        }
        {
            const int ci = t >> 7;
            const int co = (t >> 4) & 7;
            const int k = t & 15;
            const int cig = cb + ci;
            sW[ci][co][k] = (cig < Ci)
                ? w[(((size_t)(cog * 8 + co)) * Ci + cig) * 16 + k] : 0.0f;
        }
        __syncthreads();

        #pragma unroll
        for (int ci = 0; ci < 2; ci++) {
            #pragma unroll
            for (int kh = 0; kh < 4; kh++) {
                float iv[2][10];
                #pragma unroll
                for (int r2 = 0; r2 < 2; r2++) {
                    const float* rp = &sIn[ci][4 * ty + 2 * r2 + kh][8 * tx];
                    const float4 a = *reinterpret_cast<const float4*>(rp);
                    const float4 b = *reinterpret_cast<const float4*>(rp + 4);
                    const float2 c = *reinterpret_cast<const float2*>(rp + 8);
                    iv[r2][0] = a.x; iv[r2][1] = a.y; iv[r2][2] = a.z;
                    iv[r2][3] = a.w; iv[r2][4] = b.x; iv[r2][5] = b.y;
                    iv[r2][6] = b.z; iv[r2][7] = b.w; iv[r2][8] = c.x;
                    iv[r2][9] = c.y;
                }
                #pragma unroll
                for (int co = 0; co < 8; co++) {
                    const float4 wq = *reinterpret_cast<const float4*>(
                        &sW[ci][co][kh * 4]);
                    const float wv[4] = {wq.x, wq.y, wq.z, wq.w};
                    #pragma unroll
                    for (int r2 = 0; r2 < 2; r2++)
                        #pragma unroll
                        for (int c2 = 0; c2 < 4; c2++) {
                            float a = acc[co][r2 * 4 + c2];
                            #pragma unroll
                            for (int kw = 0; kw < 4; kw++)
                                a = fmaf(iv[r2][2 * c2 + kw], wv[kw], a);
                            acc[co][r2 * 4 + c2] = a;
                        }
                }
            }
        }
    }

    #pragma unroll
    for (int co = 0; co < 8; co++) {
        const float b = bias[cog * 8 + co];
        float* ob = out + ((size_t)n * Co + cog * 8 + co) * Ho * Wo;
        #pragma unroll
        for (int r2 = 0; r2 < 2; r2++) {
            const int oh = oh0 + 2 * ty + r2;
            const float4 v = make_float4(acc[co][r2 * 4 + 0] + b,
                                         acc[co][r2 * 4 + 1] + b,
                                         acc[co][r2 * 4 + 2] + b,
                                         acc[co][r2 * 4 + 3] + b);
            *reinterpret_cast<float4*>(
                ob + (size_t)oh * Wo + ow0 + 4 * tx) = v;
        }
    }
}

// ---------------------------------------------------------------------------
// 1x1 conv (fp32).
// ---------------------------------------------------------------------------
template <bool RELU, bool BIAS, bool RES>
__global__ void __launch_bounds__(256) conv1x1_k(
    const float* __restrict__ in, const float* __restrict__ w,
    const float* __restrict__ bias, const float* __restrict__ res,
    float* __restrict__ out, int Ci, int Co)
{
    __shared__ float sW1[8 * 128];
    const int n = blockIdx.z;
    const int cog = blockIdx.y;
    const int hw = blockIdx.x * 1024 + threadIdx.x * 4;
    const int t = threadIdx.x;

    for (int i = t; i < 8 * Ci; i += 256)
        sW1[i] = w[(size_t)cog * 8 * Ci + i];
    __syncthreads();

    const float* ip = in + (size_t)n * Ci * 4096 + hw;
    float4 acc[8];
    #pragma unroll
    for (int co = 0; co < 8; co++) acc[co] = make_float4(0.f, 0.f, 0.f, 0.f);

    #pragma unroll 2
    for (int ci = 0; ci < Ci; ci++) {
        const float4 xv = *reinterpret_cast<const float4*>(ip + (size_t)ci * 4096);
        #pragma unroll
        for (int co = 0; co < 8; co++) {
            const float wv = sW1[co * Ci + ci];
            acc[co].x = fmaf(xv.x, wv, acc[co].x);
            acc[co].y = fmaf(xv.y, wv, acc[co].y);
            acc[co].z = fmaf(xv.z, wv, acc[co].z);
            acc[co].w = fmaf(xv.w, wv, acc[co].w);
        }
    }

    #pragma unroll
    for (int co = 0; co < 8; co++) {
        float4 v = acc[co];
        if (BIAS) {
            const float b = bias[cog * 8 + co];
            v.x += b; v.y += b; v.z += b; v.w += b;
        }
        if (RELU) {
            v.x = fmaxf(v.x, 0.f); v.y = fmaxf(v.y, 0.f);
            v.z = fmaxf(v.z, 0.f); v.w = fmaxf(v.w, 0.f);
        }
        const size_t o = ((size_t)n * Co + cog * 8 + co) * 4096 + hw;
        if (RES) {
            const float4 r = *reinterpret_cast<const float4*>(res + o);
            v.x += r.x; v.y += r.y; v.z += r.z; v.w += r.w;
        }
        *reinterpret_cast<float4*>(out + o) = v;
    }
}

// ---------------------------------------------------------------------------
// Transposed conv k4 s2 p1 (fp32).
// ---------------------------------------------------------------------------
template <int CO_T>
__global__ void __launch_bounds__(256) deconv4x4s2_tiled(
    const float* __restrict__ in, const float* __restrict__ w,
    const float* __restrict__ bias, float* __restrict__ out,
    int Ci, int Hi, int Wi, int Co)
{
    __shared__ float sIn[8][18][36];
    __shared__ float sW[8 * CO_T * 16];

    const int n = blockIdx.z;
    const int cog = blockIdx.y;
    const int ntx = Wi >> 5;
    const int tileY = blockIdx.x / ntx;
    const int tileX = blockIdx.x - tileY * ntx;
    const int i0 = tileY * 16, j0 = tileX * 32;
    const int t = threadIdx.x;
    const int tx = t & 15, ty = t >> 4;

    float acc[CO_T][2][4];
    #pragma unroll
    for (int c = 0; c < CO_T; c++)
        #pragma unroll
        for (int a = 0; a < 2; a++)
            #pragma unroll
            for (int j = 0; j < 4; j++) acc[c][a][j] = 0.0f;

    const float* inb = in + (size_t)n * Ci * Hi * Wi;

    const int RR[2][2] = {{1, 0}, {2, 1}};
    const int KH[2][2] = {{1, 3}, {0, 2}};
    const int CC[2][2] = {{1, 0}, {2, 1}};
    const int KW[2][2] = {{1, 3}, {0, 2}};

    for (int cb = 0; cb < Ci; cb += 8) {
        __syncthreads();
        for (int i = t; i < 8 * 18 * 34; i += 256) {
            const int ci = i / 612;
            const int rem = i - ci * 612;
            const int r = rem / 34;
            const int c = rem - r * 34;
            const int ih = i0 - 1 + r;
            const int iw = j0 - 1 + c;
            float v = 0.0f;
            if (ih >= 0 && ih < Hi && iw >= 0 && iw < Wi)
                v = inb[(size_t)(cb + ci) * Hi * Wi + ih * Wi + iw];
            sIn[ci][r][c] = v;
        }
        for (int i = t; i < 8 * CO_T * 16; i += 256) {
            const int ci = i / (CO_T * 16);
            const int rem = i - ci * (CO_T * 16);
            const int co = rem >> 4;
            const int k = rem & 15;
            sW[i] = w[(((size_t)(cb + ci)) * Co + cog * CO_T + co) * 16 + k];
        }
        __syncthreads();

        #pragma unroll 1
        for (int ci = 0; ci < 8; ci++) {
            float iv[3][4];
            #pragma unroll
            for (int r = 0; r < 3; r++) {
                const float2* rp = reinterpret_cast<const float2*>(
                    &sIn[ci][ty + r][2 * tx]);
                const float2 a = rp[0], b = rp[1];
                iv[r][0] = a.x; iv[r][1] = a.y; iv[r][2] = b.x; iv[r][3] = b.y;
            }
            #pragma unroll
            for (int co = 0; co < CO_T; co++) {
                const float4* wq = reinterpret_cast<const float4*>(
                    sW + (ci * CO_T + co) * 16);
                const float4 q0 = wq[0], q1 = wq[1], q2 = wq[2], q3 = wq[3];
                float wv[16] = {q0.x, q0.y, q0.z, q0.w, q1.x, q1.y, q1.z, q1.w,
                                q2.x, q2.y, q2.z, q2.w, q3.x, q3.y, q3.z, q3.w};
                #pragma unroll
                for (int q = 0; q < 2; q++)
                    #pragma unroll
                    for (int a = 0; a < 2; a++)
                        #pragma unroll
                        for (int b = 0; b < 2; b++) {
                            float s = acc[co][a][2 * q + b];
                            #pragma unroll
                            for (int si = 0; si < 2; si++)
                                #pragma unroll
                                for (int ti = 0; ti < 2; ti++)
                                    s = fmaf(iv[RR[a][si]][q + CC[b][ti]],
                                             wv[KH[a][si] * 4 + KW[b][ti]], s);
                            acc[co][a][2 * q + b] = s;
                        }
            }
        }
    }

    const int Ho = 2 * Hi, Wo = 2 * Wi;
    const int ow = 2 * j0 + 4 * tx;
    #pragma unroll
    for (int co = 0; co < CO_T; co++) {
        const float b = bias[cog * CO_T + co];
        float* ob = out + ((size_t)n * Co + cog * CO_T + co) * Ho * Wo;
        #pragma unroll
        for (int a = 0; a < 2; a++) {
            const int oh = 2 * (i0 + ty) + a;
            *reinterpret_cast<float4*>(ob + (size_t)oh * Wo + ow) =
                make_float4(acc[co][a][0] + b, acc[co][a][1] + b,
                            acc[co][a][2] + b, acc[co][a][3] + b);
        }
    }
}

// ---------------------------------------------------------------------------
__device__ __forceinline__ float blockReduceSum(float v) {
    __shared__ float sh[32];
    #pragma unroll
    for (int o = 16; o > 0; o >>= 1) v += __shfl_down_sync(0xffffffffu, v, o);
    if ((threadIdx.x & 31) == 0) sh[threadIdx.x >> 5] = v;
    __syncthreads();
    const int nw = (blockDim.x + 31) >> 5;
    v = (threadIdx.x < (unsigned)nw) ? sh[threadIdx.x] : 0.0f;
    if (threadIdx.x < 32) {
        #pragma unroll
        for (int o = 16; o > 0; o >>= 1) v += __shfl_down_sync(0xffffffffu, v, o);
    }
    return v;
}

#define VQ_K 512
#define VQ_D 64
#define VQ_SMEM ((VQ_K * VQ_D + VQ_K) * 4)

__global__ void __launch_bounds__(256) vq_kernel(
    const float* __restrict__ z, const float* __restrict__ cb,
    float* __restrict__ q)
{
    extern __shared__ float smem[];
    float* scb = smem;
    float* snorm = smem + VQ_K * VQ_D;

    for (int i = threadIdx.x; i < VQ_K * VQ_D; i += blockDim.x)
        scb[i] = cb[i];
    __syncthreads();
    for (int c = threadIdx.x; c < VQ_K; c += blockDim.x) {
        float s = 0.0f;
        const float* cp = scb + c * VQ_D;
        #pragma unroll 16
        for (int d = 0; d < VQ_D; d++) s = fmaf(cp[d], cp[d], s);
        snorm[c] = s;
    }
    __syncthreads();

    const int pos = blockIdx.x * blockDim.x + threadIdx.x;
    const int n = pos >> 12;
    const int hw = pos & 4095;

    float zv[VQ_D];
    const float* zp = z + (size_t)n * VQ_D * 4096 + hw;
    float zn = 0.0f;
    #pragma unroll
    for (int d = 0; d < VQ_D; d++) {
        zv[d] = zp[(size_t)d * 4096];
        zn = fmaf(zv[d], zv[d], zn);
    }

    float bestd = 3.402823466e+38f;
    int besti = 0;
    for (int c = 0; c < VQ_K; c++) {
        const float4* cp4 = reinterpret_cast<const float4*>(scb + c * VQ_D);
        float dot = 0.0f;
        #pragma unroll
        for (int d4 = 0; d4 < VQ_D / 4; d4++) {
            const float4 cv = cp4[d4];
            dot = fmaf(zv[4 * d4 + 0], cv.x, dot);
            dot = fmaf(zv[4 * d4 + 1], cv.y, dot);
            dot = fmaf(zv[4 * d4 + 2], cv.z, dot);
            dot = fmaf(zv[4 * d4 + 3], cv.w, dot);
        }
        const float dist = zn - 2.0f * dot + snorm[c];
        if (dist < bestd) { bestd = dist; besti = c; }
    }

    float lsum = 0.0f;
    const float* cp = scb + besti * VQ_D;
    float* qp = q + (size_t)n * VQ_D * 4096 + hw;
    #pragma unroll
    for (int d = 0; d < VQ_D; d++) {
        const float cv = cp[d];
        qp[(size_t)d * 4096] = cv;
        const float df = zv[d] - cv;
        lsum = fmaf(df, df, lsum);
    }
    const float bsum = blockReduceSum(lsum);
    if (threadIdx.x == 0) atomicAdd(&g_vq_loss, (double)bsum);
}

__global__ void __launch_bounds__(256) recon_loss_kernel(
    const float* __restrict__ rec, const float* __restrict__ inp, int total)
{
    float lsum = 0.0f;
    for (int i = blockIdx.x * blockDim.x + threadIdx.x; i < total;
         i += gridDim.x * blockDim.x) {
        const float d = rec[i] - inp[i];
        lsum = fmaf(d, d, lsum);
    }
    const float bsum = blockReduceSum(lsum);
    if (threadIdx.x == 0) atomicAdd(&g_rec_loss, (double)bsum);
}

__global__ void finalize_kernel(float* out, int out_size) {
    const double recon = g_rec_loss / 3145728.0;
    const double vq = g_vq_loss / 4194304.0;
    out[out_size - 2] = (float)(recon + 1.25 * vq);
    out[out_size - 1] = (float)recon;
}

// ---------------------------------------------------------------------------
extern "C" void kernel_launch(void* const* d_in, const int* in_sizes, int n_in,
                              void* d_out, int out_size)
{
    const float* inp        = (const float*)d_in[0];
    const float* enc_w1     = (const float*)d_in[1];
    const float* enc_b1     = (const float*)d_in[2];
    const float* enc_w2     = (const float*)d_in[3];
    const float* enc_b2     = (const float*)d_in[4];
    const float* enc_w3     = (const float*)d_in[5];
    const float* enc_b3     = (const float*)d_in[6];
    const float* enc_res_w1 = (const float*)d_in[7];
    const float* enc_res_w2 = (const float*)d_in[8];
    const float* vq_w       = (const float*)d_in[9];
    const float* vq_b       = (const float*)d_in[10];
    const float* codebook   = (const float*)d_in[11];
    const float* dec_w1     = (const float*)d_in[12];
    const float* dec_b1     = (const float*)d_in[13];
    const float* dec_res_w1 = (const float*)d_in[14];
    const float* dec_res_w2 = (const float*)d_in[15];
    const float* dec_w2t    = (const float*)d_in[16];
    const float* dec_b2     = (const float*)d_in[17];
    const float* dec_w3t    = (const float*)d_in[18];
    const float* dec_b3     = (const float*)d_in[19];

    float *bufA, *bufB, *bufC, *half, *zb, *qb, *d1, *d2, *eb;
    cudaGetSymbolAddress((void**)&bufA, g_bufA);
    cudaGetSymbolAddress((void**)&bufB, g_bufB);
    cudaGetSymbolAddress((void**)&bufC, g_bufC);
    cudaGetSymbolAddress((void**)&half, g_half);
    cudaGetSymbolAddress((void**)&zb, g_z);
    cudaGetSymbolAddress((void**)&qb, g_q);
    cudaGetSymbolAddress((void**)&d1, g_d1);
    cudaGetSymbolAddress((void**)&d2, g_d2);
    cudaGetSymbolAddress((void**)&eb, g_e);

    cudaFuncSetAttribute(vq_kernel, cudaFuncAttributeMaxDynamicSharedMemorySize,
                         VQ_SMEM);
    cudaFuncSetAttribute(conv4x4s2_big,
                         cudaFuncAttributeMaxDynamicSharedMemorySize, K4B_SMEM);
    cudaFuncSetAttribute(conv3x3_pipe<false, true>,
                         cudaFuncAttributeMaxDynamicSharedMemorySize, C3P_SMEM);
    cudaFuncSetAttribute(conv3x3_pipe<true, false>,
                         cudaFuncAttributeMaxDynamicSharedMemorySize, C3P_SMEM);

    zero_losses_kernel<<<1, 1>>>();

    // ---- Encoder ----
    conv4x4s2_big<<<dim3(8, 8, NB), 256, K4B_SMEM>>>(
        inp, enc_w1, enc_b1, bufA, 3, 256, 256, 64, 2);
    conv4x4s2_big<<<dim3(2, 16, NB), 256, K4B_SMEM>>>(
        bufA, enc_w2, enc_b2, bufB, 64, 128, 128, 128, 1);
    conv3x3_pipe<false, true><<<dim3(2, 16, NB), 256, C3P_SMEM>>>(
        bufB, enc_w3, enc_b3, bufC, 128, 128);

    {
        float* cur = bufC;
        float* alt = bufB;
        for (int i = 0; i < 3; i++) {
            conv3x3_pipe<true, false><<<dim3(2, 8, NB), 256, C3P_SMEM>>>(
                cur, enc_res_w1 + (size_t)i * 64 * 128 * 9, nullptr, half,
                128, 64);
            conv1x1_k<true, false, true><<<dim3(4, 16, NB), 256>>>(
                half, enc_res_w2 + (size_t)i * 128 * 64, nullptr, cur, alt,
                64, 128);
            float* t = cur; cur = alt; alt = t;
        }
        conv1x1_k<false, true, false><<<dim3(4, 8, NB), 256>>>(
            cur, vq_w, vq_b, nullptr, zb, 128, 64);
    }

    // ---- VQ ----
    vq_kernel<<<256, 256, VQ_SMEM>>>(zb, codebook, qb);

    // ---- Decoder ----
    conv3x3_pipe<false, true><<<dim3(2, 8, NB), 256, C3P_SMEM>>>(
        qb, dec_w1, dec_b1, d1, 64, 64);
    {
        float* cur = d1;
        float* alt = d2;
        for (int i = 0; i < 3; i++) {
            conv3x3_pipe<true, false><<<dim3(2, 4, NB), 256, C3P_SMEM>>>(
                cur, dec_res_w1 + (size_t)i * 32 * 64 * 9, nullptr, half,
                64, 32);
            conv1x1_k<true, false, true><<<dim3(4, 8, NB), 256>>>(
                half, dec_res_w2 + (size_t)i * 64 * 32, nullptr, cur, alt,
                32, 64);
            float* t = cur; cur = alt; alt = t;
        }
        deconv4x4s2_tiled<4><<<dim3(8, 8, NB), 256>>>(
            cur, dec_w2t, dec_b2, eb, 64, 64, 64, 32);
    }
    deconv4x4s2_tiled<3><<<dim3(32, 1, NB), 256>>>(
        eb, dec_w3t, dec_b3, (float*)d_out, 32, 128, 128, 3);

    // ---- Losses ----
    recon_loss_kernel<<<1024, 256>>>((const float*)d_out, inp, 3145728);
    finalize_kernel<<<1, 1>>>((float*)d_out, out_size);
}

// round 12
// speedup vs baseline: 1.2887x; 1.0454x over previous
#include <cuda_runtime.h>
#include <cstdint>

// ---------------------------------------------------------------------------
// VQ-VAE forward, sm_100a. Round 11:
//  - conv4x4s2_pipe: cp.async 2-stage pipeline for enc1/enc2 (unit-granular
//    zfill staging, no conditional scalar halo).
//  - conv3x3_pipe gains tile-height template RPT; RPT=1 for dec_res launches
//    (grid 128 -> 256 blocks, fills 148 SMs).
// Everything else identical to round 10.
// ---------------------------------------------------------------------------

#define NB 16

__device__ float g_bufA[(size_t)NB * 64 * 128 * 128];
__device__ float g_bufB[(size_t)NB * 128 * 64 * 64];
__device__ float g_bufC[(size_t)NB * 128 * 64 * 64];
__device__ float g_half[(size_t)NB * 64 * 64 * 64];
__device__ float g_z[(size_t)NB * 64 * 64 * 64];
__device__ float g_q[(size_t)NB * 64 * 64 * 64];
__device__ float g_d1[(size_t)NB * 64 * 64 * 64];
__device__ float g_d2[(size_t)NB * 64 * 64 * 64];
__device__ float g_e[(size_t)NB * 32 * 128 * 128];
__device__ double g_vq_loss;
__device__ double g_rec_loss;

__global__ void zero_losses_kernel() {
    g_vq_loss = 0.0;
    g_rec_loss = 0.0;
}

// ---------------------------------------------------------------------------
// cp.async helpers
// ---------------------------------------------------------------------------
__device__ __forceinline__ void cp_async16(uint32_t dst, const void* src,
                                           int src_size) {
    asm volatile("cp.async.ca.shared.global [%0], [%1], 16, %2;"
                 :: "r"(dst), "l"(src), "r"(src_size));
}
__device__ __forceinline__ void cp_async4(uint32_t dst, const void* src) {
    asm volatile("cp.async.ca.shared.global [%0], [%1], 4;"
                 :: "r"(dst), "l"(src));
}
__device__ __forceinline__ void cp_commit() {
    asm volatile("cp.async.commit_group;");
}
template <int N>
__device__ __forceinline__ void cp_wait() {
    asm volatile("cp.async.wait_group %0;" :: "n"(N));
}

// ---------------------------------------------------------------------------
// 3x3 conv s1 p1, H=W=64, cp.async double-buffered. Block 256 (16x16).
// Block tile: (16*RPT) rows x 64 cols x 8 co. Thread: RPT x 4 out x 8 co.
// smem: sIn[2][4][16*RPT+2][68] — data cols 0..63 (16B aligned), cols 64..67
// permanently zero (right halo + left-halo slot at col 66). Row OOB via
// cp.async zfill. sW[2][8][4][12]. 4-ci chunks, stage c+1 while computing c.
// grid = (64/(16*RPT), Co/8, N)
// ---------------------------------------------------------------------------
#define C3P_SMEM(RPT) ((2 * 4 * (16 * (RPT) + 2) * 68 + 2 * 8 * 4 * 12) * 4)

template <int RPT, bool RELU, bool BIAS>
__global__ void __launch_bounds__(256, 2) conv3x3_pipe(
    const float* __restrict__ in, const float* __restrict__ w,
    const float* __restrict__ bias, float* __restrict__ out,
    int Ci, int Co)
{
    constexpr int SROWS = 16 * RPT + 2;
    extern __shared__ float sm[];
    float* sInBase = sm;                      // [ (s*4+ci)*SROWS + r ][68]
    float* sWBase = sm + 2 * 4 * SROWS * 68;  // [ ((s*8+co)*4+ci) ][12]

    const int n = blockIdx.z;
    const int cog = blockIdx.y;
    const int oh0 = blockIdx.x * (16 * RPT);
    const int t = threadIdx.x;
    const int tx = t & 15, ty = t >> 4;
    const int c16 = t & 15, rr = t >> 4;

    // zero pad cols 64..67 of all rows (both stages) — written once
    for (int i = t; i < 2 * 4 * SROWS; i += 256) {
        float* row = sInBase + i * 68;
        row[64] = 0.f; row[65] = 0.f; row[66] = 0.f; row[67] = 0.f;
    }

    float acc[8][4 * RPT];
    #pragma unroll
    for (int i = 0; i < 8; i++)
        #pragma unroll
        for (int j = 0; j < 4 * RPT; j++) acc[i][j] = 0.0f;

    const float* inb = in + (size_t)n * Ci * 4096;
    const float* wb = w + (size_t)cog * 8 * Ci * 9;

    auto stage_chunk = [&](int chunk, int s) {
        const int cbase = chunk * 4;
        #pragma unroll
        for (int ci = 0; ci < 4; ci++) {
            const float* g = inb + (size_t)(cbase + ci) * 4096;
            float* srow0 = sInBase + (size_t)((s * 4 + ci) * SROWS) * 68;
            #pragma unroll
            for (int r = rr; r < SROWS; r += 16) {
                const int ih = oh0 - 1 + r;
                const bool ok = (ih >= 0 && ih < 64);
                const int ihc = ok ? ih : 0;
                const uint32_t dst = (uint32_t)__cvta_generic_to_shared(
                    srow0 + r * 68 + c16 * 4);
                cp_async16(dst, g + ihc * 64 + c16 * 4, ok ? 16 : 0);
            }
        }
        for (int i = t; i < 288; i += 256) {
            const int co = i / 36;
            const int rem = i - co * 36;
            const int ci = rem / 9;
            const int k = rem - ci * 9;
            const uint32_t dst = (uint32_t)__cvta_generic_to_shared(
                sWBase + ((s * 8 + co) * 4 + ci) * 12 + k);
            cp_async4(dst, wb + ((size_t)co * Ci + cbase + ci) * 9 + k);
        }
    };

    const int nch = Ci >> 2;
    stage_chunk(0, 0);
    cp_commit();

    for (int c = 0; c < nch; c++) {
        if (c + 1 < nch) { stage_chunk(c + 1, (c + 1) & 1); cp_commit(); }
        if (c + 1 < nch) cp_wait<1>(); else cp_wait<0>();
        __syncthreads();

        const int s = c & 1;
        #pragma unroll 1
        for (int ci = 0; ci < 4; ci++) {
            const float* rowb = sInBase + (size_t)((s * 4 + ci) * SROWS) * 68;
            float iv[RPT + 2][6];
            #pragma unroll
            for (int r = 0; r < RPT + 2; r++) {
                const float* rp = rowb + (RPT * ty + r) * 68;
                const float4 a = *reinterpret_cast<const float4*>(rp + 4 * tx);
                const float lf = (tx == 0) ? rp[66] : rp[4 * tx - 1];
                const float rg = rp[4 * tx + 4];
                iv[r][0] = lf;  iv[r][1] = a.x; iv[r][2] = a.y;
                iv[r][3] = a.z; iv[r][4] = a.w; iv[r][5] = rg;
            }
            #pragma unroll
            for (int co = 0; co < 8; co++) {
                const float* wp = sWBase + ((s * 8 + co) * 4 + ci) * 12;
                const float4 w0 = *reinterpret_cast<const float4*>(wp);
                const float4 w1 = *reinterpret_cast<const float4*>(wp + 4);
                const float w8 = wp[8];
                const float wv[9] = {w0.x, w0.y, w0.z, w0.w,
                                     w1.x, w1.y, w1.z, w1.w, w8};
                #pragma unroll
                for (int r2 = 0; r2 < RPT; r2++)
                    #pragma unroll
                    for (int c2 = 0; c2 < 4; c2++) {
                        float a2 = acc[co][r2 * 4 + c2];
                        #pragma unroll
                        for (int kh = 0; kh < 3; kh++)
                            #pragma unroll
                            for (int kw = 0; kw < 3; kw++)
                                a2 = fmaf(iv[r2 + kh][c2 + kw],
                                          wv[kh * 3 + kw], a2);
                        acc[co][r2 * 4 + c2] = a2;
                    }
            }
        }
        __syncthreads();
    }

    float* outb = out + ((size_t)n * Co + cog * 8) * 4096;
    #pragma unroll
    for (int co = 0; co < 8; co++) {
        const float b = BIAS ? bias[cog * 8 + co] : 0.0f;
        #pragma unroll
        for (int r2 = 0; r2 < RPT; r2++) {
            const int oh = oh0 + RPT * ty + r2;
            float4 v = make_float4(acc[co][r2 * 4 + 0] + b,
                                   acc[co][r2 * 4 + 1] + b,
                                   acc[co][r2 * 4 + 2] + b,
                                   acc[co][r2 * 4 + 3] + b);
            if (RELU) {
                v.x = fmaxf(v.x, 0.f); v.y = fmaxf(v.y, 0.f);
                v.z = fmaxf(v.z, 0.f); v.w = fmaxf(v.w, 0.f);
            }
            *reinterpret_cast<float4*>(
                outb + (size_t)co * 4096 + oh * 64 + 4 * tx) = v;
        }
    }
}

// ---------------------------------------------------------------------------
// 4x4 stride-2 pad-1 conv, cp.async double-buffered. Block 256 (16x16).
// Block tile: 32 out-rows x 64 out-cols x 8 co. Thread: 2x4 out x 8 co.
// smem sIn[2][66][136]: row r = input row 2*oh0-1+r; col j = global col
// 2*ow0-4+j (start 16B aligned since ow0 % 64 == 0). Staged as 66x34 16B
// units per ci; OOB units (row or col) -> zfill. No scalar halo path at all.
// 1-ci chunks; stage ci+1 while computing ci. grid=(tiles, Co/8, N).
// ---------------------------------------------------------------------------
#define K4P_SMEM ((2 * 66 * 136 + 2 * 8 * 16) * 4)

__global__ void __launch_bounds__(256, 2) conv4x4s2_pipe(
    const float* __restrict__ in, const float* __restrict__ w,
    const float* __restrict__ bias, float* __restrict__ out,
    int Ci, int Hi, int Wi, int Co, int ntx)
{
    extern __shared__ float sm[];
    float* sInB = sm;                     // [s][66][136]
    float* sWB = sm + 2 * 66 * 136;       // [s][co][16]

    const int Ho = Hi >> 1, Wo = Wi >> 1;
    const int n = blockIdx.z;
    const int cog = blockIdx.y;
    const int tileY = blockIdx.x / ntx;
    const int tileX = blockIdx.x - tileY * ntx;
    const int oh0 = tileY * 32, ow0 = tileX * 64;
    const int t = threadIdx.x;
    const int tx = t & 15, ty = t >> 4;
    const int gc0 = 2 * ow0 - 4;

    float acc[8][8];
    #pragma unroll
    for (int i = 0; i < 8; i++)
        #pragma unroll
        for (int j = 0; j < 8; j++) acc[i][j] = 0.0f;

    const float* inb = in + (size_t)n * Ci * Hi * Wi;

    auto stage = [&](int ci, int s) {
        const float* g = inb + (size_t)ci * Hi * Wi;
        float* sIn = sInB + s * 66 * 136;
        for (int i = t; i < 66 * 34; i += 256) {
            const int r = i / 34;
            const int u = i - r * 34;
            const int ih = 2 * oh0 - 1 + r;
            const int gc = gc0 + 4 * u;
            const bool ok = (ih >= 0) && (ih < Hi) && (gc >= 0) && (gc + 3 < Wi);
            const int iha = ok ? ih : 0;
            const int gca = ok ? gc : 0;
            const uint32_t dst = (uint32_t)__cvta_generic_to_shared(
                sIn + r * 136 + 4 * u);
            cp_async16(dst, g + (size_t)iha * Wi + gca, ok ? 16 : 0);
        }
        if (t < 32) {
            const int co = t >> 2, quad = t & 3;
            const uint32_t dst = (uint32_t)__cvta_generic_to_shared(
                sWB + (s * 8 + co) * 16 + 4 * quad);
            cp_async16(dst,
                       w + ((size_t)(cog * 8 + co) * Ci + ci) * 16 + 4 * quad,
                       16);
        }
    };

    stage(0, 0);
    cp_commit();

    for (int ci = 0; ci < Ci; ci++) {
        if (ci + 1 < Ci) { stage(ci + 1, (ci + 1) & 1); cp_commit(); }
        if (ci + 1 < Ci) cp_wait<1>(); else cp_wait<0>();
        __syncthreads();

        const int s = ci & 1;
        const float* sIn = sInB + s * 66 * 136;
        #pragma unroll
        for (int kh = 0; kh < 4; kh++) {
            // out row r2 uses input row rel 4*ty + 2*r2 + kh;
            // thread out cols 4tx..4tx+3 use cols rel 8tx+3 .. 8tx+12.
            float iv[2][10];
            #pragma unroll
            for (int r2 = 0; r2 < 2; r2++) {
                const float* rp = sIn + (4 * ty + 2 * r2 + kh) * 136 + 8 * tx;
                const float s0 = rp[3];
                const float4 a = *reinterpret_cast<const float4*>(rp + 4);
                const float4 b = *reinterpret_cast<const float4*>(rp + 8);
                const float s1 = rp[12];
                iv[r2][0] = s0;  iv[r2][1] = a.x; iv[r2][2] = a.y;
                iv[r2][3] = a.z; iv[r2][4] = a.w; iv[r2][5] = b.x;
                iv[r2][6] = b.y; iv[r2][7] = b.z; iv[r2][8] = b.w;
                iv[r2][9] = s1;
            }
            #pragma unroll
            for (int co = 0; co < 8; co++) {
                const float4 wq = *reinterpret_cast<const float4*>(
                    sWB + (s * 8 + co) * 16 + kh * 4);
                const float wv[4] = {wq.x, wq.y, wq.z, wq.w};
                #pragma unroll
                for (int r2 = 0; r2 < 2; r2++)
                    #pragma unroll
                    for (int c2 = 0; c2 < 4; c2++) {
                        float a = acc[co][r2 * 4 + c2];
                        #pragma unroll
                        for (int kw = 0; kw < 4; kw++)
                            a = fmaf(iv[r2][2 * c2 + kw], wv[kw], a);
                        acc[co][r2 * 4 + c2] = a;
                    }
            }
        }
        __syncthreads();
    }

    #pragma unroll
    for (int co = 0; co < 8; co++) {
        const float b = bias[cog * 8 + co];
        float* ob = out + ((size_t)n * Co + cog * 8 + co) * Ho * Wo;
        #pragma unroll
        for (int r2 = 0; r2 < 2; r2++) {
            const int oh = oh0 + 2 * ty + r2;
            const float4 v = make_float4(acc[co][r2 * 4 + 0] + b,
                                         acc[co][r2 * 4 + 1] + b,
                                         acc[co][r2 * 4 + 2] + b,
                                         acc[co][r2 * 4 + 3] + b);
            *reinterpret_cast<float4*>(
                ob + (size_t)oh * Wo + ow0 + 4 * tx) = v;
        }
    }
}

// ---------------------------------------------------------------------------
// 1x1 conv (fp32).
// ---------------------------------------------------------------------------
template <bool RELU, bool BIAS, bool RES>
__global__ void __launch_bounds__(256) conv1x1_k(
    const float* __restrict__ in, const float* __restrict__ w,
    const float* __restrict__ bias, const float* __restrict__ res,
    float* __restrict__ out, int Ci, int Co)
{
    __shared__ float sW1[8 * 128];
    const int n = blockIdx.z;
    const int cog = blockIdx.y;
    const int hw = blockIdx.x * 1024 + threadIdx.x * 4;
    const int t = threadIdx.x;

    for (int i = t; i < 8 * Ci; i += 256)
        sW1[i] = w[(size_t)cog * 8 * Ci + i];
    __syncthreads();

    const float* ip = in + (size_t)n * Ci * 4096 + hw;
    float4 acc[8];
    #pragma unroll
    for (int co = 0; co < 8; co++) acc[co] = make_float4(0.f, 0.f, 0.f, 0.f);

    #pragma unroll 2
    for (int ci = 0; ci < Ci; ci++) {
        const float4 xv = *reinterpret_cast<const float4*>(ip + (size_t)ci * 4096);
        #pragma unroll
        for (int co = 0; co < 8; co++) {
            const float wv = sW1[co * Ci + ci];
            acc[co].x = fmaf(xv.x, wv, acc[co].x);
            acc[co].y = fmaf(xv.y, wv, acc[co].y);
            acc[co].z = fmaf(xv.z, wv, acc[co].z);
            acc[co].w = fmaf(xv.w, wv, acc[co].w);
        }
    }

    #pragma unroll
    for (int co = 0; co < 8; co++) {
        float4 v = acc[co];
        if (BIAS) {
            const float b = bias[cog * 8 + co];
            v.x += b; v.y += b; v.z += b; v.w += b;
        }
        if (RELU) {
            v.x = fmaxf(v.x, 0.f); v.y = fmaxf(v.y, 0.f);
            v.z = fmaxf(v.z, 0.f); v.w = fmaxf(v.w, 0.f);
        }
        const size_t o = ((size_t)n * Co + cog * 8 + co) * 4096 + hw;
        if (RES) {
            const float4 r = *reinterpret_cast<const float4*>(res + o);
            v.x += r.x; v.y += r.y; v.z += r.z; v.w += r.w;
        }
        *reinterpret_cast<float4*>(out + o) = v;
    }
}

// ---------------------------------------------------------------------------
// Transposed conv k4 s2 p1 (fp32).
// ---------------------------------------------------------------------------
template <int CO_T>
__global__ void __launch_bounds__(256) deconv4x4s2_tiled(
    const float* __restrict__ in, const float* __restrict__ w,
    const float* __restrict__ bias, float* __restrict__ out,
    int Ci, int Hi, int Wi, int Co)
{
    __shared__ float sIn[8][18][36];
    __shared__ float sW[8 * CO_T * 16];

    const int n = blockIdx.z;
    const int cog = blockIdx.y;
    const int ntx = Wi >> 5;
    const int tileY = blockIdx.x / ntx;
    const int tileX = blockIdx.x - tileY * ntx;
    const int i0 = tileY * 16, j0 = tileX * 32;
    const int t = threadIdx.x;
    const int tx = t & 15, ty = t >> 4;

    float acc[CO_T][2][4];
    #pragma unroll
    for (int c = 0; c < CO_T; c++)
        #pragma unroll
        for (int a = 0; a < 2; a++)
            #pragma unroll
            for (int j = 0; j < 4; j++) acc[c][a][j] = 0.0f;

    const float* inb = in + (size_t)n * Ci * Hi * Wi;

    const int RR[2][2] = {{1, 0}, {2, 1}};
    const int KH[2][2] = {{1, 3}, {0, 2}};
    const int CC[2][2] = {{1, 0}, {2, 1}};
    const int KW[2][2] = {{1, 3}, {0, 2}};

    for (int cb = 0; cb < Ci; cb += 8) {
        __syncthreads();
        for (int i = t; i < 8 * 18 * 34; i += 256) {
            const int ci = i / 612;
            const int rem = i - ci * 612;
            const int r = rem / 34;
            const int c = rem - r * 34;
            const int ih = i0 - 1 + r;
            const int iw = j0 - 1 + c;
            float v = 0.0f;
            if (ih >= 0 && ih < Hi && iw >= 0 && iw < Wi)
                v = inb[(size_t)(cb + ci) * Hi * Wi + ih * Wi + iw];
            sIn[ci][r][c] = v;
        }
        for (int i = t; i < 8 * CO_T * 16; i += 256) {
            const int ci = i / (CO_T * 16);
            const int rem = i - ci * (CO_T * 16);
            const int co = rem >> 4;
            const int k = rem & 15;
            sW[i] = w[(((size_t)(cb + ci)) * Co + cog * CO_T + co) * 16 + k];
        }
        __syncthreads();

        #pragma unroll 1
        for (int ci = 0; ci < 8; ci++) {
            float iv[3][4];
            #pragma unroll
            for (int r = 0; r < 3; r++) {
                const float2* rp = reinterpret_cast<const float2*>(
                    &sIn[ci][ty + r][2 * tx]);
                const float2 a = rp[0], b = rp[1];
                iv[r][0] = a.x; iv[r][1] = a.y; iv[r][2] = b.x; iv[r][3] = b.y;
            }
            #pragma unroll
            for (int co = 0; co < CO_T; co++) {
                const float4* wq = reinterpret_cast<const float4*>(
                    sW + (ci * CO_T + co) * 16);
                const float4 q0 = wq[0], q1 = wq[1], q2 = wq[2], q3 = wq[3];
                float wv[16] = {q0.x, q0.y, q0.z, q0.w, q1.x, q1.y, q1.z, q1.w,
                                q2.x, q2.y, q2.z, q2.w, q3.x, q3.y, q3.z, q3.w};
                #pragma unroll
                for (int q = 0; q < 2; q++)
                    #pragma unroll
                    for (int a = 0; a < 2; a++)
                        #pragma unroll
                        for (int b = 0; b < 2; b++) {
                            float s = acc[co][a][2 * q + b];
                            #pragma unroll
                            for (int si = 0; si < 2; si++)
                                #pragma unroll
                                for (int ti = 0; ti < 2; ti++)
                                    s = fmaf(iv[RR[a][si]][q + CC[b][ti]],
                                             wv[KH[a][si] * 4 + KW[b][ti]], s);
                            acc[co][a][2 * q + b] = s;
                        }
            }
        }
    }

    const int Ho = 2 * Hi, Wo = 2 * Wi;
    const int ow = 2 * j0 + 4 * tx;
    #pragma unroll
    for (int co = 0; co < CO_T; co++) {
        const float b = bias[cog * CO_T + co];
        float* ob = out + ((size_t)n * Co + cog * CO_T + co) * Ho * Wo;
        #pragma unroll
        for (int a = 0; a < 2; a++) {
            const int oh = 2 * (i0 + ty) + a;
            *reinterpret_cast<float4*>(ob + (size_t)oh * Wo + ow) =
                make_float4(acc[co][a][0] + b, acc[co][a][1] + b,
                            acc[co][a][2] + b, acc[co][a][3] + b);
        }
    }
}

// ---------------------------------------------------------------------------
__device__ __forceinline__ float blockReduceSum(float v) {
    __shared__ float sh[32];
    #pragma unroll
    for (int o = 16; o > 0; o >>= 1) v += __shfl_down_sync(0xffffffffu, v, o);
    if ((threadIdx.x & 31) == 0) sh[threadIdx.x >> 5] = v;
    __syncthreads();
    const int nw = (blockDim.x + 31) >> 5;
    v = (threadIdx.x < (unsigned)nw) ? sh[threadIdx.x] : 0.0f;
    if (threadIdx.x < 32) {
        #pragma unroll
        for (int o = 16; o > 0; o >>= 1) v += __shfl_down_sync(0xffffffffu, v, o);
    }
    return v;
}

#define VQ_K 512
#define VQ_D 64
#define VQ_SMEM ((VQ_K * VQ_D + VQ_K) * 4)

__global__ void __launch_bounds__(256) vq_kernel(
    const float* __restrict__ z, const float* __restrict__ cb,
    float* __restrict__ q)
{
    extern __shared__ float smem[];
    float* scb = smem;
    float* snorm = smem + VQ_K * VQ_D;

    for (int i = threadIdx.x; i < VQ_K * VQ_D; i += blockDim.x)
        scb[i] = cb[i];
    __syncthreads();
    for (int c = threadIdx.x; c < VQ_K; c += blockDim.x) {
        float s = 0.0f;
        const float* cp = scb + c * VQ_D;
        #pragma unroll 16
        for (int d = 0; d < VQ_D; d++) s = fmaf(cp[d], cp[d], s);
        snorm[c] = s;
    }
    __syncthreads();

    const int pos = blockIdx.x * blockDim.x + threadIdx.x;
    const int n = pos >> 12;
    const int hw = pos & 4095;

    float zv[VQ_D];
    const float* zp = z + (size_t)n * VQ_D * 4096 + hw;
    float zn = 0.0f;
    #pragma unroll
    for (int d = 0; d < VQ_D; d++) {
        zv[d] = zp[(size_t)d * 4096];
        zn = fmaf(zv[d], zv[d], zn);
    }

    float bestd = 3.402823466e+38f;
    int besti = 0;
    for (int c = 0; c < VQ_K; c++) {
        const float4* cp4 = reinterpret_cast<const float4*>(scb + c * VQ_D);
        float dot = 0.0f;
        #pragma unroll
        for (int d4 = 0; d4 < VQ_D / 4; d4++) {
            const float4 cv = cp4[d4];
            dot = fmaf(zv[4 * d4 + 0], cv.x, dot);
            dot = fmaf(zv[4 * d4 + 1], cv.y, dot);
            dot = fmaf(zv[4 * d4 + 2], cv.z, dot);
            dot = fmaf(zv[4 * d4 + 3], cv.w, dot);
        }
        const float dist = zn - 2.0f * dot + snorm[c];
        if (dist < bestd) { bestd = dist; besti = c; }
    }

    float lsum = 0.0f;
    const float* cp = scb + besti * VQ_D;
    float* qp = q + (size_t)n * VQ_D * 4096 + hw;
    #pragma unroll
    for (int d = 0; d < VQ_D; d++) {
        const float cv = cp[d];
        qp[(size_t)d * 4096] = cv;
        const float df = zv[d] - cv;
        lsum = fmaf(df, df, lsum);
    }
    const float bsum = blockReduceSum(lsum);
    if (threadIdx.x == 0) atomicAdd(&g_vq_loss, (double)bsum);
}

__global__ void __launch_bounds__(256) recon_loss_kernel(
    const float* __restrict__ rec, const float* __restrict__ inp, int total)
{
    float lsum = 0.0f;
    for (int i = blockIdx.x * blockDim.x + threadIdx.x; i < total;
         i += gridDim.x * blockDim.x) {
        const float d = rec[i] - inp[i];
        lsum = fmaf(d, d, lsum);
    }
    const float bsum = blockReduceSum(lsum);
    if (threadIdx.x == 0) atomicAdd(&g_rec_loss, (double)bsum);
}

__global__ void finalize_kernel(float* out, int out_size) {
    const double recon = g_rec_loss / 3145728.0;
    const double vq = g_vq_loss / 4194304.0;
    out[out_size - 2] = (float)(recon + 1.25 * vq);
    out[out_size - 1] = (float)recon;
}

// ---------------------------------------------------------------------------
extern "C" void kernel_launch(void* const* d_in, const int* in_sizes, int n_in,
                              void* d_out, int out_size)
{
    const float* inp        = (const float*)d_in[0];
    const float* enc_w1     = (const float*)d_in[1];
    const float* enc_b1     = (const float*)d_in[2];
    const float* enc_w2     = (const float*)d_in[3];
    const float* enc_b2     = (const float*)d_in[4];
    const float* enc_w3     = (const float*)d_in[5];
    const float* enc_b3     = (const float*)d_in[6];
    const float* enc_res_w1 = (const float*)d_in[7];
    const float* enc_res_w2 = (const float*)d_in[8];
    const float* vq_w       = (const float*)d_in[9];
    const float* vq_b       = (const float*)d_in[10];
    const float* codebook   = (const float*)d_in[11];
    const float* dec_w1     = (const float*)d_in[12];
    const float* dec_b1     = (const float*)d_in[13];
    const float* dec_res_w1 = (const float*)d_in[14];
    const float* dec_res_w2 = (const float*)d_in[15];
    const float* dec_w2t    = (const float*)d_in[16];
    const float* dec_b2     = (const float*)d_in[17];
    const float* dec_w3t    = (const float*)d_in[18];
    const float* dec_b3     = (const float*)d_in[19];

    float *bufA, *bufB, *bufC, *half, *zb, *qb, *d1, *d2, *eb;
    cudaGetSymbolAddress((void**)&bufA, g_bufA);
    cudaGetSymbolAddress((void**)&bufB, g_bufB);
    cudaGetSymbolAddress((void**)&bufC, g_bufC);
    cudaGetSymbolAddress((void**)&half, g_half);
    cudaGetSymbolAddress((void**)&zb, g_z);
    cudaGetSymbolAddress((void**)&qb, g_q);
    cudaGetSymbolAddress((void**)&d1, g_d1);
    cudaGetSymbolAddress((void**)&d2, g_d2);
    cudaGetSymbolAddress((void**)&eb, g_e);

    cudaFuncSetAttribute(vq_kernel, cudaFuncAttributeMaxDynamicSharedMemorySize,
                         VQ_SMEM);
    cudaFuncSetAttribute(conv4x4s2_pipe,
                         cudaFuncAttributeMaxDynamicSharedMemorySize, K4P_SMEM);
    cudaFuncSetAttribute(conv3x3_pipe<2, false, true>,
                         cudaFuncAttributeMaxDynamicSharedMemorySize,
                         C3P_SMEM(2));
    cudaFuncSetAttribute(conv3x3_pipe<2, true, false>,
                         cudaFuncAttributeMaxDynamicSharedMemorySize,
                         C3P_SMEM(2));
    cudaFuncSetAttribute(conv3x3_pipe<1, true, false>,
                         cudaFuncAttributeMaxDynamicSharedMemorySize,
                         C3P_SMEM(1));

    zero_losses_kernel<<<1, 1>>>();

    // ---- Encoder ----
    // enc1: 3->64, 256->128. tiles = (128/32)*(128/64) = 8, ntx = 2
    conv4x4s2_pipe<<<dim3(8, 8, NB), 256, K4P_SMEM>>>(
        inp, enc_w1, enc_b1, bufA, 3, 256, 256, 64, 2);
    // enc2: 64->128, 128->64. tiles = (64/32)*(64/64) = 2, ntx = 1
    conv4x4s2_pipe<<<dim3(2, 16, NB), 256, K4P_SMEM>>>(
        bufA, enc_w2, enc_b2, bufB, 64, 128, 128, 128, 1);
    // enc3: 128->128, 3x3
    conv3x3_pipe<2, false, true><<<dim3(2, 16, NB), 256, C3P_SMEM(2)>>>(
        bufB, enc_w3, enc_b3, bufC, 128, 128);

    {
        float* cur = bufC;
        float* alt = bufB;
        for (int i = 0; i < 3; i++) {
            conv3x3_pipe<2, true, false><<<dim3(2, 8, NB), 256, C3P_SMEM(2)>>>(
                cur, enc_res_w1 + (size_t)i * 64 * 128 * 9, nullptr, half,
                128, 64);
            conv1x1_k<true, false, true><<<dim3(4, 16, NB), 256>>>(
                half, enc_res_w2 + (size_t)i * 128 * 64, nullptr, cur, alt,
                64, 128);
            float* t = cur; cur = alt; alt = t;
        }
        conv1x1_k<false, true, false><<<dim3(4, 8, NB), 256>>>(
            cur, vq_w, vq_b, nullptr, zb, 128, 64);
    }

    // ---- VQ ----
    vq_kernel<<<256, 256, VQ_SMEM>>>(zb, codebook, qb);

    // ---- Decoder ----
    conv3x3_pipe<2, false, true><<<dim3(2, 8, NB), 256, C3P_SMEM(2)>>>(
        qb, dec_w1, dec_b1, d1, 64, 64);
    {
        float* cur = d1;
        float* alt = d2;
        for (int i = 0; i < 3; i++) {
            // RPT=1: 16-row tiles -> grid (4,4,16) = 256 blocks (fills chip)
            conv3x3_pipe<1, true, false><<<dim3(4, 4, NB), 256, C3P_SMEM(1)>>>(
                cur, dec_res_w1 + (size_t)i * 32 * 64 * 9, nullptr, half,
                64, 32);
            conv1x1_k<true, false, true><<<dim3(4, 8, NB), 256>>>(
                half, dec_res_w2 + (size_t)i * 64 * 32, nullptr, cur, alt,
                32, 64);
            float* t = cur; cur = alt; alt = t;
        }
        deconv4x4s2_tiled<4><<<dim3(8, 8, NB), 256>>>(
            cur, dec_w2t, dec_b2, eb, 64, 64, 64, 32);
    }
    deconv4x4s2_tiled<3><<<dim3(32, 1, NB), 256>>>(
        eb, dec_w3t, dec_b3, (float*)d_out, 32, 128, 128, 3);

    // ---- Losses ----
    recon_loss_kernel<<<1024, 256>>>((const float*)d_out, inp, 3145728);
    finalize_kernel<<<1, 1>>>((float*)d_out, out_size);
}

// round 13
// speedup vs baseline: 1.3469x; 1.0451x over previous
#include <cuda_runtime.h>
#include <cstdint>

// ---------------------------------------------------------------------------
// VQ-VAE forward, sm_100a. Round 12:
//  - single-barrier pipeline loop (wait -> sync -> stage(c+1) -> compute(c))
//    for conv3x3_pipe and conv4x4s2_pipe (halves barrier count);
//  - deconv4x4s2_pipe: cp.async port of the transposed conv (unit-granular
//    zfill staging, coverage by construction).
// Everything else identical to round 11.
// ---------------------------------------------------------------------------

#define NB 16

__device__ float g_bufA[(size_t)NB * 64 * 128 * 128];
__device__ float g_bufB[(size_t)NB * 128 * 64 * 64];
__device__ float g_bufC[(size_t)NB * 128 * 64 * 64];
__device__ float g_half[(size_t)NB * 64 * 64 * 64];
__device__ float g_z[(size_t)NB * 64 * 64 * 64];
__device__ float g_q[(size_t)NB * 64 * 64 * 64];
__device__ float g_d1[(size_t)NB * 64 * 64 * 64];
__device__ float g_d2[(size_t)NB * 64 * 64 * 64];
__device__ float g_e[(size_t)NB * 32 * 128 * 128];
__device__ double g_vq_loss;
__device__ double g_rec_loss;

__global__ void zero_losses_kernel() {
    g_vq_loss = 0.0;
    g_rec_loss = 0.0;
}

// ---------------------------------------------------------------------------
// cp.async helpers
// ---------------------------------------------------------------------------
__device__ __forceinline__ void cp_async16(uint32_t dst, const void* src,
                                           int src_size) {
    asm volatile("cp.async.ca.shared.global [%0], [%1], 16, %2;"
                 :: "r"(dst), "l"(src), "r"(src_size));
}
__device__ __forceinline__ void cp_async4(uint32_t dst, const void* src) {
    asm volatile("cp.async.ca.shared.global [%0], [%1], 4;"
                 :: "r"(dst), "l"(src));
}
__device__ __forceinline__ void cp_commit() {
    asm volatile("cp.async.commit_group;");
}
template <int N>
__device__ __forceinline__ void cp_wait() {
    asm volatile("cp.async.wait_group %0;" :: "n"(N));
}

// ---------------------------------------------------------------------------
// 3x3 conv s1 p1, H=W=64, cp.async double-buffered, single barrier/chunk.
// Block 256 (16x16). Block tile: (16*RPT) rows x 64 cols x 8 co.
// smem: sIn[2][4][16*RPT+2][68], cols 64..67 permanently zero. sW[2][8][4][12].
// grid = (64/(16*RPT), Co/8, N)
// ---------------------------------------------------------------------------
#define C3P_SMEM(RPT) ((2 * 4 * (16 * (RPT) + 2) * 68 + 2 * 8 * 4 * 12) * 4)

template <int RPT, bool RELU, bool BIAS>
__global__ void __launch_bounds__(256, 2) conv3x3_pipe(
    const float* __restrict__ in, const float* __restrict__ w,
    const float* __restrict__ bias, float* __restrict__ out,
    int Ci, int Co)
{
    constexpr int SROWS = 16 * RPT + 2;
    extern __shared__ float sm[];
    float* sInBase = sm;
    float* sWBase = sm + 2 * 4 * SROWS * 68;

    const int n = blockIdx.z;
    const int cog = blockIdx.y;
    const int oh0 = blockIdx.x * (16 * RPT);
    const int t = threadIdx.x;
    const int tx = t & 15, ty = t >> 4;
    const int c16 = t & 15, rr = t >> 4;

    for (int i = t; i < 2 * 4 * SROWS; i += 256) {
        float* row = sInBase + i * 68;
        row[64] = 0.f; row[65] = 0.f; row[66] = 0.f; row[67] = 0.f;
    }

    float acc[8][4 * RPT];
    #pragma unroll
    for (int i = 0; i < 8; i++)
        #pragma unroll
        for (int j = 0; j < 4 * RPT; j++) acc[i][j] = 0.0f;

    const float* inb = in + (size_t)n * Ci * 4096;
    const float* wb = w + (size_t)cog * 8 * Ci * 9;

    auto stage_chunk = [&](int chunk, int s) {
        const int cbase = chunk * 4;
        #pragma unroll
        for (int ci = 0; ci < 4; ci++) {
            const float* g = inb + (size_t)(cbase + ci) * 4096;
            float* srow0 = sInBase + (size_t)((s * 4 + ci) * SROWS) * 68;
            #pragma unroll
            for (int r = rr; r < SROWS; r += 16) {
                const int ih = oh0 - 1 + r;
                const bool ok = (ih >= 0 && ih < 64);
                const int ihc = ok ? ih : 0;
                const uint32_t dst = (uint32_t)__cvta_generic_to_shared(
                    srow0 + r * 68 + c16 * 4);
                cp_async16(dst, g + ihc * 64 + c16 * 4, ok ? 16 : 0);
            }
        }
        for (int i = t; i < 288; i += 256) {
            const int co = i / 36;
            const int rem = i - co * 36;
            const int ci = rem / 9;
            const int k = rem - ci * 9;
            const uint32_t dst = (uint32_t)__cvta_generic_to_shared(
                sWBase + ((s * 8 + co) * 4 + ci) * 12 + k);
            cp_async4(dst, wb + ((size_t)co * Ci + cbase + ci) * 9 + k);
        }
    };

    const int nch = Ci >> 2;
    stage_chunk(0, 0);
    cp_commit();

    for (int c = 0; c < nch; c++) {
        cp_wait<0>();
        __syncthreads();   // all threads done computing chunk c-1; data of c visible
        if (c + 1 < nch) { stage_chunk(c + 1, (c + 1) & 1); cp_commit(); }

        const int s = c & 1;
        #pragma unroll 1
        for (int ci = 0; ci < 4; ci++) {
            const float* rowb = sInBase + (size_t)((s * 4 + ci) * SROWS) * 68;
            float iv[RPT + 2][6];
            #pragma unroll
            for (int r = 0; r < RPT + 2; r++) {
                const float* rp = rowb + (RPT * ty + r) * 68;
                const float4 a = *reinterpret_cast<const float4*>(rp + 4 * tx);
                const float lf = (tx == 0) ? rp[66] : rp[4 * tx - 1];
                const float rg = rp[4 * tx + 4];
                iv[r][0] = lf;  iv[r][1] = a.x; iv[r][2] = a.y;
                iv[r][3] = a.z; iv[r][4] = a.w; iv[r][5] = rg;
            }
            #pragma unroll
            for (int co = 0; co < 8; co++) {
                const float* wp = sWBase + ((s * 8 + co) * 4 + ci) * 12;
                const float4 w0 = *reinterpret_cast<const float4*>(wp);
                const float4 w1 = *reinterpret_cast<const float4*>(wp + 4);
                const float w8 = wp[8];
                const float wv[9] = {w0.x, w0.y, w0.z, w0.w,
                                     w1.x, w1.y, w1.z, w1.w, w8};
                #pragma unroll
                for (int r2 = 0; r2 < RPT; r2++)
                    #pragma unroll
                    for (int c2 = 0; c2 < 4; c2++) {
                        float a2 = acc[co][r2 * 4 + c2];
                        #pragma unroll
                        for (int kh = 0; kh < 3; kh++)
                            #pragma unroll
                            for (int kw = 0; kw < 3; kw++)
                                a2 = fmaf(iv[r2 + kh][c2 + kw],
                                          wv[kh * 3 + kw], a2);
                        acc[co][r2 * 4 + c2] = a2;
                    }
            }
        }
    }

    float* outb = out + ((size_t)n * Co + cog * 8) * 4096;
    #pragma unroll
    for (int co = 0; co < 8; co++) {
        const float b = BIAS ? bias[cog * 8 + co] : 0.0f;
        #pragma unroll
        for (int r2 = 0; r2 < RPT; r2++) {
            const int oh = oh0 + RPT * ty + r2;
            float4 v = make_float4(acc[co][r2 * 4 + 0] + b,
                                   acc[co][r2 * 4 + 1] + b,
                                   acc[co][r2 * 4 + 2] + b,
                                   acc[co][r2 * 4 + 3] + b);
            if (RELU) {
                v.x = fmaxf(v.x, 0.f); v.y = fmaxf(v.y, 0.f);
                v.z = fmaxf(v.z, 0.f); v.w = fmaxf(v.w, 0.f);
            }
            *reinterpret_cast<float4*>(
                outb + (size_t)co * 4096 + oh * 64 + 4 * tx) = v;
        }
    }
}

// ---------------------------------------------------------------------------
// 4x4 stride-2 pad-1 conv, cp.async double-buffered, single barrier/chunk.
// Block 256 (16x16). Block tile: 32 out-rows x 64 out-cols x 8 co.
// smem sIn[2][66][136]: col j = global col 2*ow0-4+j. 66x34 16B units/ci,
// OOB -> zfill. 1-ci chunks. grid=(tiles, Co/8, N).
// ---------------------------------------------------------------------------
#define K4P_SMEM ((2 * 66 * 136 + 2 * 8 * 16) * 4)

__global__ void __launch_bounds__(256, 2) conv4x4s2_pipe(
    const float* __restrict__ in, const float* __restrict__ w,
    const float* __restrict__ bias, float* __restrict__ out,
    int Ci, int Hi, int Wi, int Co, int ntx)
{
    extern __shared__ float sm[];
    float* sInB = sm;
    float* sWB = sm + 2 * 66 * 136;

    const int Ho = Hi >> 1, Wo = Wi >> 1;
    const int n = blockIdx.z;
    const int cog = blockIdx.y;
    const int tileY = blockIdx.x / ntx;
    const int tileX = blockIdx.x - tileY * ntx;
    const int oh0 = tileY * 32, ow0 = tileX * 64;
    const int t = threadIdx.x;
    const int tx = t & 15, ty = t >> 4;
    const int gc0 = 2 * ow0 - 4;

    float acc[8][8];
    #pragma unroll
    for (int i = 0; i < 8; i++)
        #pragma unroll
        for (int j = 0; j < 8; j++) acc[i][j] = 0.0f;

    const float* inb = in + (size_t)n * Ci * Hi * Wi;

    auto stage = [&](int ci, int s) {
        const float* g = inb + (size_t)ci * Hi * Wi;
        float* sIn = sInB + s * 66 * 136;
        for (int i = t; i < 66 * 34; i += 256) {
            const int r = i / 34;
            const int u = i - r * 34;
            const int ih = 2 * oh0 - 1 + r;
            const int gc = gc0 + 4 * u;
            const bool ok = (ih >= 0) && (ih < Hi) && (gc >= 0) && (gc + 3 < Wi);
            const int iha = ok ? ih : 0;
            const int gca = ok ? gc : 0;
            const uint32_t dst = (uint32_t)__cvta_generic_to_shared(
                sIn + r * 136 + 4 * u);
            cp_async16(dst, g + (size_t)iha * Wi + gca, ok ? 16 : 0);
        }
        if (t < 32) {
            const int co = t >> 2, quad = t & 3;
            const uint32_t dst = (uint32_t)__cvta_generic_to_shared(
                sWB + (s * 8 + co) * 16 + 4 * quad);
            cp_async16(dst,
                       w + ((size_t)(cog * 8 + co) * Ci + ci) * 16 + 4 * quad,
                       16);
        }
    };

    stage(0, 0);
    cp_commit();

    for (int ci = 0; ci < Ci; ci++) {
        cp_wait<0>();
        __syncthreads();
        if (ci + 1 < Ci) { stage(ci + 1, (ci + 1) & 1); cp_commit(); }

        const int s = ci & 1;
        const float* sIn = sInB + s * 66 * 136;
        #pragma unroll
        for (int kh = 0; kh < 4; kh++) {
            float iv[2][10];
            #pragma unroll
            for (int r2 = 0; r2 < 2; r2++) {
                const float* rp = sIn + (4 * ty + 2 * r2 + kh) * 136 + 8 * tx;
                const float s0 = rp[3];
                const float4 a = *reinterpret_cast<const float4*>(rp + 4);
                const float4 b = *reinterpret_cast<const float4*>(rp + 8);
                const float s1 = rp[12];
                iv[r2][0] = s0;  iv[r2][1] = a.x; iv[r2][2] = a.y;
                iv[r2][3] = a.z; iv[r2][4] = a.w; iv[r2][5] = b.x;
                iv[r2][6] = b.y; iv[r2][7] = b.z; iv[r2][8] = b.w;
                iv[r2][9] = s1;
            }
            #pragma unroll
            for (int co = 0; co < 8; co++) {
                const float4 wq = *reinterpret_cast<const float4*>(
                    sWB + (s * 8 + co) * 16 + kh * 4);
                const float wv[4] = {wq.x, wq.y, wq.z, wq.w};
                #pragma unroll
                for (int r2 = 0; r2 < 2; r2++)
                    #pragma unroll
                    for (int c2 = 0; c2 < 4; c2++) {
                        float a = acc[co][r2 * 4 + c2];
                        #pragma unroll
                        for (int kw = 0; kw < 4; kw++)
                            a = fmaf(iv[r2][2 * c2 + kw], wv[kw], a);
                        acc[co][r2 * 4 + c2] = a;
                    }
            }
        }
    }

    #pragma unroll
    for (int co = 0; co < 8; co++) {
        const float b = bias[cog * 8 + co];
        float* ob = out + ((size_t)n * Co + cog * 8 + co) * Ho * Wo;
        #pragma unroll
        for (int r2 = 0; r2 < 2; r2++) {
            const int oh = oh0 + 2 * ty + r2;
            const float4 v = make_float4(acc[co][r2 * 4 + 0] + b,
                                         acc[co][r2 * 4 + 1] + b,
                                         acc[co][r2 * 4 + 2] + b,
                                         acc[co][r2 * 4 + 3] + b);
            *reinterpret_cast<float4*>(
                ob + (size_t)oh * Wo + ow0 + 4 * tx) = v;
        }
    }
}

// ---------------------------------------------------------------------------
// 1x1 conv (fp32, unchanged).
// ---------------------------------------------------------------------------
template <bool RELU, bool BIAS, bool RES>
__global__ void __launch_bounds__(256) conv1x1_k(
    const float* __restrict__ in, const float* __restrict__ w,
    const float* __restrict__ bias, const float* __restrict__ res,
    float* __restrict__ out, int Ci, int Co)
{
    __shared__ float sW1[8 * 128];
    const int n = blockIdx.z;
    const int cog = blockIdx.y;
    const int hw = blockIdx.x * 1024 + threadIdx.x * 4;
    const int t = threadIdx.x;

    for (int i = t; i < 8 * Ci; i += 256)
        sW1[i] = w[(size_t)cog * 8 * Ci + i];
    __syncthreads();

    const float* ip = in + (size_t)n * Ci * 4096 + hw;
    float4 acc[8];
    #pragma unroll
    for (int co = 0; co < 8; co++) acc[co] = make_float4(0.f, 0.f, 0.f, 0.f);

    #pragma unroll 2
    for (int ci = 0; ci < Ci; ci++) {
        const float4 xv = *reinterpret_cast<const float4*>(ip + (size_t)ci * 4096);
        #pragma unroll
        for (int co = 0; co < 8; co++) {
            const float wv = sW1[co * Ci + ci];
            acc[co].x = fmaf(xv.x, wv, acc[co].x);
            acc[co].y = fmaf(xv.y, wv, acc[co].y);
            acc[co].z = fmaf(xv.z, wv, acc[co].z);
            acc[co].w = fmaf(xv.w, wv, acc[co].w);
        }
    }

    #pragma unroll
    for (int co = 0; co < 8; co++) {
        float4 v = acc[co];
        if (BIAS) {
            const float b = bias[cog * 8 + co];
            v.x += b; v.y += b; v.z += b; v.w += b;
        }
        if (RELU) {
            v.x = fmaxf(v.x, 0.f); v.y = fmaxf(v.y, 0.f);
            v.z = fmaxf(v.z, 0.f); v.w = fmaxf(v.w, 0.f);
        }
        const size_t o = ((size_t)n * Co + cog * 8 + co) * 4096 + hw;
        if (RES) {
            const float4 r = *reinterpret_cast<const float4*>(res + o);
            v.x += r.x; v.y += r.y; v.z += r.z; v.w += r.w;
        }
        *reinterpret_cast<float4*>(out + o) = v;
    }
}

// ---------------------------------------------------------------------------
// Transposed conv k4 s2 p1, cp.async double-buffered, single barrier/chunk.
// Block 256 (16x16). Thread: 2 quads (2x4 outputs) x CO_T co.
// smem sIn[2][8][18][44]: col j = global col j0-4+j (staged as 18x10 16B
// units/ci, OOB -> zfill; Wi % 4 == 0 so no partial units).
// sW[2][8][CO_T][16]. 8-ci chunks. grid = ((Hi/16)*(Wi/32), Co/CO_T, N)
// ---------------------------------------------------------------------------
#define DC_SMEM(CO_T) ((2 * 8 * 18 * 44 + 2 * 8 * (CO_T) * 16) * 4)

template <int CO_T>
__global__ void __launch_bounds__(256, 2) deconv4x4s2_pipe(
    const float* __restrict__ in, const float* __restrict__ w,
    const float* __restrict__ bias, float* __restrict__ out,
    int Ci, int Hi, int Wi, int Co)
{
    extern __shared__ float sm[];
    float* sInB = sm;                          // [s][ci][18][44]
    float* sWB = sm + 2 * 8 * 18 * 44;         // [s][ci][CO_T][16]

    const int n = blockIdx.z;
    const int cog = blockIdx.y;
    const int ntx = Wi >> 5;
    const int tileY = blockIdx.x / ntx;
    const int tileX = blockIdx.x - tileY * ntx;
    const int i0 = tileY * 16, j0 = tileX * 32;
    const int t = threadIdx.x;
    const int tx = t & 15, ty = t >> 4;
    const int gc0 = j0 - 4;

    float acc[CO_T][2][4];
    #pragma unroll
    for (int c = 0; c < CO_T; c++)
        #pragma unroll
        for (int a = 0; a < 2; a++)
            #pragma unroll
            for (int j = 0; j < 4; j++) acc[c][a][j] = 0.0f;

    const float* inb = in + (size_t)n * Ci * Hi * Wi;

    const int RR[2][2] = {{1, 0}, {2, 1}};
    const int KH[2][2] = {{1, 3}, {0, 2}};
    const int CC[2][2] = {{1, 0}, {2, 1}};
    const int KW[2][2] = {{1, 3}, {0, 2}};

    auto stage = [&](int chunk, int s) {
        const int cb = chunk * 8;
        // inputs: 8 ci x 18 rows x 10 units
        for (int i = t; i < 8 * 18 * 10; i += 256) {
            const int ci = i / 180;
            const int rem = i - ci * 180;
            const int r = rem / 10;
            const int u = rem - r * 10;
            const int ih = i0 - 1 + r;
            const int gc = gc0 + 4 * u;
            const bool ok = (ih >= 0) && (ih < Hi) && (gc >= 0) && (gc + 3 < Wi);
            const int iha = ok ? ih : 0;
            const int gca = ok ? gc : 0;
            const uint32_t dst = (uint32_t)__cvta_generic_to_shared(
                sInB + ((s * 8 + ci) * 18 + r) * 44 + 4 * u);
            cp_async16(dst, inb + (size_t)(cb + ci) * Hi * Wi +
                            (size_t)iha * Wi + gca, ok ? 16 : 0);
        }
        // weights: 8 ci x CO_T co x 4 units
        for (int i = t; i < 8 * CO_T * 4; i += 256) {
            const int ci = i / (CO_T * 4);
            const int rem = i - ci * (CO_T * 4);
            const int co = rem >> 2;
            const int quad = rem & 3;
            const uint32_t dst = (uint32_t)__cvta_generic_to_shared(
                sWB + ((s * 8 + ci) * CO_T + co) * 16 + 4 * quad);
            cp_async16(dst,
                       w + (((size_t)(cb + ci)) * Co + cog * CO_T + co) * 16 +
                           4 * quad, 16);
        }
    };

    const int nch = Ci >> 3;
    stage(0, 0);
    cp_commit();

    for (int c = 0; c < nch; c++) {
        cp_wait<0>();
        __syncthreads();
        if (c + 1 < nch) { stage(c + 1, (c + 1) & 1); cp_commit(); }

        const int s = c & 1;
        #pragma unroll 1
        for (int ci = 0; ci < 8; ci++) {
            const float* rowb = sInB + (size_t)((s * 8 + ci) * 18) * 44;
            float iv[3][4];
            #pragma unroll
            for (int r = 0; r < 3; r++) {
                const float* rp = rowb + (ty + r) * 44 + 3 + 2 * tx;
                iv[r][0] = rp[0]; iv[r][1] = rp[1];
                iv[r][2] = rp[2]; iv[r][3] = rp[3];
            }
            #pragma unroll
            for (int co = 0; co < CO_T; co++) {
                const float* wp = sWB + ((s * 8 + ci) * CO_T + co) * 16;
                const float4 q0 = *reinterpret_cast<const float4*>(wp);
                const float4 q1 = *reinterpret_cast<const float4*>(wp + 4);
                const float4 q2 = *reinterpret_cast<const float4*>(wp + 8);
                const float4 q3 = *reinterpret_cast<const float4*>(wp + 12);
                float wv[16] = {q0.x, q0.y, q0.z, q0.w, q1.x, q1.y, q1.z, q1.w,
                                q2.x, q2.y, q2.z, q2.w, q3.x, q3.y, q3.z, q3.w};
                #pragma unroll
                for (int q = 0; q < 2; q++)
                    #pragma unroll
                    for (int a = 0; a < 2; a++)
                        #pragma unroll
                        for (int b = 0; b < 2; b++) {
                            float sv = acc[co][a][2 * q + b];
                            #pragma unroll
                            for (int si = 0; si < 2; si++)
                                #pragma unroll
                                for (int ti = 0; ti < 2; ti++)
                                    sv = fmaf(iv[RR[a][si]][q + CC[b][ti]],
                                              wv[KH[a][si] * 4 + KW[b][ti]], sv);
                            acc[co][a][2 * q + b] = sv;
                        }
            }
        }
    }

    const int Ho = 2 * Hi, Wo = 2 * Wi;
    const int ow = 2 * j0 + 4 * tx;
    #pragma unroll
    for (int co = 0; co < CO_T; co++) {
        const float b = bias[cog * CO_T + co];
        float* ob = out + ((size_t)n * Co + cog * CO_T + co) * Ho * Wo;
        #pragma unroll
        for (int a = 0; a < 2; a++) {
            const int oh = 2 * (i0 + ty) + a;
            *reinterpret_cast<float4*>(ob + (size_t)oh * Wo + ow) =
                make_float4(acc[co][a][0] + b, acc[co][a][1] + b,
                            acc[co][a][2] + b, acc[co][a][3] + b);
        }
    }
}

// ---------------------------------------------------------------------------
__device__ __forceinline__ float blockReduceSum(float v) {
    __shared__ float sh[32];
    #pragma unroll
    for (int o = 16; o > 0; o >>= 1) v += __shfl_down_sync(0xffffffffu, v, o);
    if ((threadIdx.x & 31) == 0) sh[threadIdx.x >> 5] = v;
    __syncthreads();
    const int nw = (blockDim.x + 31) >> 5;
    v = (threadIdx.x < (unsigned)nw) ? sh[threadIdx.x] : 0.0f;
    if (threadIdx.x < 32) {
        #pragma unroll
        for (int o = 16; o > 0; o >>= 1) v += __shfl_down_sync(0xffffffffu, v, o);
    }
    return v;
}

#define VQ_K 512
#define VQ_D 64
#define VQ_SMEM ((VQ_K * VQ_D + VQ_K) * 4)

__global__ void __launch_bounds__(256) vq_kernel(
    const float* __restrict__ z, const float* __restrict__ cb,
    float* __restrict__ q)
{
    extern __shared__ float smem[];
    float* scb = smem;
    float* snorm = smem + VQ_K * VQ_D;

    for (int i = threadIdx.x; i < VQ_K * VQ_D; i += blockDim.x)
        scb[i] = cb[i];
    __syncthreads();
    for (int c = threadIdx.x; c < VQ_K; c += blockDim.x) {
        float s = 0.0f;
        const float* cp = scb + c * VQ_D;
        #pragma unroll 16
        for (int d = 0; d < VQ_D; d++) s = fmaf(cp[d], cp[d], s);
        snorm[c] = s;
    }
    __syncthreads();

    const int pos = blockIdx.x * blockDim.x + threadIdx.x;
    const int n = pos >> 12;
    const int hw = pos & 4095;

    float zv[VQ_D];
    const float* zp = z + (size_t)n * VQ_D * 4096 + hw;
    float zn = 0.0f;
    #pragma unroll
    for (int d = 0; d < VQ_D; d++) {
        zv[d] = zp[(size_t)d * 4096];
        zn = fmaf(zv[d], zv[d], zn);
    }

    float bestd = 3.402823466e+38f;
    int besti = 0;
    for (int c = 0; c < VQ_K; c++) {
        const float4* cp4 = reinterpret_cast<const float4*>(scb + c * VQ_D);
        float dot = 0.0f;
        #pragma unroll
        for (int d4 = 0; d4 < VQ_D / 4; d4++) {
            const float4 cv = cp4[d4];
            dot = fmaf(zv[4 * d4 + 0], cv.x, dot);
            dot = fmaf(zv[4 * d4 + 1], cv.y, dot);
            dot = fmaf(zv[4 * d4 + 2], cv.z, dot);
            dot = fmaf(zv[4 * d4 + 3], cv.w, dot);
        }
        const float dist = zn - 2.0f * dot + snorm[c];
        if (dist < bestd) { bestd = dist; besti = c; }
    }

    float lsum = 0.0f;
    const float* cp = scb + besti * VQ_D;
    float* qp = q + (size_t)n * VQ_D * 4096 + hw;
    #pragma unroll
    for (int d = 0; d < VQ_D; d++) {
        const float cv = cp[d];
        qp[(size_t)d * 4096] = cv;
        const float df = zv[d] - cv;
        lsum = fmaf(df, df, lsum);
    }
    const float bsum = blockReduceSum(lsum);
    if (threadIdx.x == 0) atomicAdd(&g_vq_loss, (double)bsum);
}

__global__ void __launch_bounds__(256) recon_loss_kernel(
    const float* __restrict__ rec, const float* __restrict__ inp, int total)
{
    float lsum = 0.0f;
    for (int i = blockIdx.x * blockDim.x + threadIdx.x; i < total;
         i += gridDim.x * blockDim.x) {
        const float d = rec[i] - inp[i];
        lsum = fmaf(d, d, lsum);
    }
    const float bsum = blockReduceSum(lsum);
    if (threadIdx.x == 0) atomicAdd(&g_rec_loss, (double)bsum);
}

__global__ void finalize_kernel(float* out, int out_size) {
    const double recon = g_rec_loss / 3145728.0;
    const double vq = g_vq_loss / 4194304.0;
    out[out_size - 2] = (float)(recon + 1.25 * vq);
    out[out_size - 1] = (float)recon;
}

// ---------------------------------------------------------------------------
extern "C" void kernel_launch(void* const* d_in, const int* in_sizes, int n_in,
                              void* d_out, int out_size)
{
    const float* inp        = (const float*)d_in[0];
    const float* enc_w1     = (const float*)d_in[1];
    const float* enc_b1     = (const float*)d_in[2];
    const float* enc_w2     = (const float*)d_in[3];
    const float* enc_b2     = (const float*)d_in[4];
    const float* enc_w3     = (const float*)d_in[5];
    const float* enc_b3     = (const float*)d_in[6];
    const float* enc_res_w1 = (const float*)d_in[7];
    const float* enc_res_w2 = (const float*)d_in[8];
    const float* vq_w       = (const float*)d_in[9];
    const float* vq_b       = (const float*)d_in[10];
    const float* codebook   = (const float*)d_in[11];
    const float* dec_w1     = (const float*)d_in[12];
    const float* dec_b1     = (const float*)d_in[13];
    const float* dec_res_w1 = (const float*)d_in[14];
    const float* dec_res_w2 = (const float*)d_in[15];
    const float* dec_w2t    = (const float*)d_in[16];
    const float* dec_b2     = (const float*)d_in[17];
    const float* dec_w3t    = (const float*)d_in[18];
    const float* dec_b3     = (const float*)d_in[19];

    float *bufA, *bufB, *bufC, *half, *zb, *qb, *d1, *d2, *eb;
    cudaGetSymbolAddress((void**)&bufA, g_bufA);
    cudaGetSymbolAddress((void**)&bufB, g_bufB);
    cudaGetSymbolAddress((void**)&bufC, g_bufC);
    cudaGetSymbolAddress((void**)&half, g_half);
    cudaGetSymbolAddress((void**)&zb, g_z);
    cudaGetSymbolAddress((void**)&qb, g_q);
    cudaGetSymbolAddress((void**)&d1, g_d1);
    cudaGetSymbolAddress((void**)&d2, g_d2);
    cudaGetSymbolAddress((void**)&eb, g_e);

    cudaFuncSetAttribute(vq_kernel, cudaFuncAttributeMaxDynamicSharedMemorySize,
                         VQ_SMEM);
    cudaFuncSetAttribute(conv4x4s2_pipe,
                         cudaFuncAttributeMaxDynamicSharedMemorySize, K4P_SMEM);
    cudaFuncSetAttribute(conv3x3_pipe<2, false, true>,
                         cudaFuncAttributeMaxDynamicSharedMemorySize,
                         C3P_SMEM(2));
    cudaFuncSetAttribute(conv3x3_pipe<2, true, false>,
                         cudaFuncAttributeMaxDynamicSharedMemorySize,
                         C3P_SMEM(2));
    cudaFuncSetAttribute(conv3x3_pipe<1, true, false>,
                         cudaFuncAttributeMaxDynamicSharedMemorySize,
                         C3P_SMEM(1));
    cudaFuncSetAttribute(deconv4x4s2_pipe<4>,
                         cudaFuncAttributeMaxDynamicSharedMemorySize,
                         DC_SMEM(4));
    cudaFuncSetAttribute(deconv4x4s2_pipe<3>,
                         cudaFuncAttributeMaxDynamicSharedMemorySize,
                         DC_SMEM(3));

    zero_losses_kernel<<<1, 1>>>();

    // ---- Encoder ----
    conv4x4s2_pipe<<<dim3(8, 8, NB), 256, K4P_SMEM>>>(
        inp, enc_w1, enc_b1, bufA, 3, 256, 256, 64, 2);
    conv4x4s2_pipe<<<dim3(2, 16, NB), 256, K4P_SMEM>>>(
        bufA, enc_w2, enc_b2, bufB, 64, 128, 128, 128, 1);
    conv3x3_pipe<2, false, true><<<dim3(2, 16, NB), 256, C3P_SMEM(2)>>>(
        bufB, enc_w3, enc_b3, bufC, 128, 128);

    {
        float* cur = bufC;
        float* alt = bufB;
        for (int i = 0; i < 3; i++) {
            conv3x3_pipe<2, true, false><<<dim3(2, 8, NB), 256, C3P_SMEM(2)>>>(
                cur, enc_res_w1 + (size_t)i * 64 * 128 * 9, nullptr, half,
                128, 64);
            conv1x1_k<true, false, true><<<dim3(4, 16, NB), 256>>>(
                half, enc_res_w2 + (size_t)i * 128 * 64, nullptr, cur, alt,
                64, 128);
            float* t = cur; cur = alt; alt = t;
        }
        conv1x1_k<false, true, false><<<dim3(4, 8, NB), 256>>>(
            cur, vq_w, vq_b, nullptr, zb, 128, 64);
    }

    // ---- VQ ----
    vq_kernel<<<256, 256, VQ_SMEM>>>(zb, codebook, qb);

    // ---- Decoder ----
    conv3x3_pipe<2, false, true><<<dim3(2, 8, NB), 256, C3P_SMEM(2)>>>(
        qb, dec_w1, dec_b1, d1, 64, 64);
    {
        float* cur = d1;
        float* alt = d2;
        for (int i = 0; i < 3; i++) {
            conv3x3_pipe<1, true, false><<<dim3(4, 4, NB), 256, C3P_SMEM(1)>>>(
                cur, dec_res_w1 + (size_t)i * 32 * 64 * 9, nullptr, half,
                64, 32);
            conv1x1_k<true, false, true><<<dim3(4, 8, NB), 256>>>(
                half, dec_res_w2 + (size_t)i * 64 * 32, nullptr, cur, alt,
                32, 64);
            float* t = cur; cur = alt; alt = t;
        }
        deconv4x4s2_pipe<4><<<dim3(8, 8, NB), 256, DC_SMEM(4)>>>(
            cur, dec_w2t, dec_b2, eb, 64, 64, 64, 32);
    }
    deconv4x4s2_pipe<3><<<dim3(32, 1, NB), 256, DC_SMEM(3)>>>(
        eb, dec_w3t, dec_b3, (float*)d_out, 32, 128, 128, 3);

    // ---- Losses ----
    recon_loss_kernel<<<1024, 256>>>((const float*)d_out, inp, 3145728);
    finalize_kernel<<<1, 1>>>((float*)d_out, out_size);
}

// round 14
// speedup vs baseline: 1.3555x; 1.0065x over previous
#include <cuda_runtime.h>
#include <cstdint>

// ---------------------------------------------------------------------------
// VQ-VAE forward, sm_100a. Round 13: R12 convs + (a) recon loss fused into
// deconv2 epilogue, (b) persistent VQ (grid 148, codebook staged once/block),
// (c) conv1x1 unroll 4.
// ---------------------------------------------------------------------------

#define NB 16

__device__ float g_bufA[(size_t)NB * 64 * 128 * 128];
__device__ float g_bufB[(size_t)NB * 128 * 64 * 64];
__device__ float g_bufC[(size_t)NB * 128 * 64 * 64];
__device__ float g_half[(size_t)NB * 64 * 64 * 64];
__device__ float g_z[(size_t)NB * 64 * 64 * 64];
__device__ float g_q[(size_t)NB * 64 * 64 * 64];
__device__ float g_d1[(size_t)NB * 64 * 64 * 64];
__device__ float g_d2[(size_t)NB * 64 * 64 * 64];
__device__ float g_e[(size_t)NB * 32 * 128 * 128];
__device__ double g_vq_loss;
__device__ double g_rec_loss;

__global__ void zero_losses_kernel() {
    g_vq_loss = 0.0;
    g_rec_loss = 0.0;
}

// ---------------------------------------------------------------------------
// cp.async helpers
// ---------------------------------------------------------------------------
__device__ __forceinline__ void cp_async16(uint32_t dst, const void* src,
                                           int src_size) {
    asm volatile("cp.async.ca.shared.global [%0], [%1], 16, %2;"
                 :: "r"(dst), "l"(src), "r"(src_size));
}
__device__ __forceinline__ void cp_async4(uint32_t dst, const void* src) {
    asm volatile("cp.async.ca.shared.global [%0], [%1], 4;"
                 :: "r"(dst), "l"(src));
}
__device__ __forceinline__ void cp_commit() {
    asm volatile("cp.async.commit_group;");
}
template <int N>
__device__ __forceinline__ void cp_wait() {
    asm volatile("cp.async.wait_group %0;" :: "n"(N));
}

// ---------------------------------------------------------------------------
__device__ __forceinline__ float blockReduceSum(float v) {
    __shared__ float sh[32];
    #pragma unroll
    for (int o = 16; o > 0; o >>= 1) v += __shfl_down_sync(0xffffffffu, v, o);
    if ((threadIdx.x & 31) == 0) sh[threadIdx.x >> 5] = v;
    __syncthreads();
    const int nw = (blockDim.x + 31) >> 5;
    v = (threadIdx.x < (unsigned)nw) ? sh[threadIdx.x] : 0.0f;
    if (threadIdx.x < 32) {
        #pragma unroll
        for (int o = 16; o > 0; o >>= 1) v += __shfl_down_sync(0xffffffffu, v, o);
    }
    return v;
}

// ---------------------------------------------------------------------------
// 3x3 conv s1 p1, H=W=64, cp.async double-buffered, single barrier/chunk.
// ---------------------------------------------------------------------------
#define C3P_SMEM(RPT) ((2 * 4 * (16 * (RPT) + 2) * 68 + 2 * 8 * 4 * 12) * 4)

template <int RPT, bool RELU, bool BIAS>
__global__ void __launch_bounds__(256, 2) conv3x3_pipe(
    const float* __restrict__ in, const float* __restrict__ w,
    const float* __restrict__ bias, float* __restrict__ out,
    int Ci, int Co)
{
    constexpr int SROWS = 16 * RPT + 2;
    extern __shared__ float sm[];
    float* sInBase = sm;
    float* sWBase = sm + 2 * 4 * SROWS * 68;

    const int n = blockIdx.z;
    const int cog = blockIdx.y;
    const int oh0 = blockIdx.x * (16 * RPT);
    const int t = threadIdx.x;
    const int tx = t & 15, ty = t >> 4;
    const int c16 = t & 15, rr = t >> 4;

    for (int i = t; i < 2 * 4 * SROWS; i += 256) {
        float* row = sInBase + i * 68;
        row[64] = 0.f; row[65] = 0.f; row[66] = 0.f; row[67] = 0.f;
    }

    float acc[8][4 * RPT];
    #pragma unroll
    for (int i = 0; i < 8; i++)
        #pragma unroll
        for (int j = 0; j < 4 * RPT; j++) acc[i][j] = 0.0f;

    const float* inb = in + (size_t)n * Ci * 4096;
    const float* wb = w + (size_t)cog * 8 * Ci * 9;

    auto stage_chunk = [&](int chunk, int s) {
        const int cbase = chunk * 4;
        #pragma unroll
        for (int ci = 0; ci < 4; ci++) {
            const float* g = inb + (size_t)(cbase + ci) * 4096;
            float* srow0 = sInBase + (size_t)((s * 4 + ci) * SROWS) * 68;
            #pragma unroll
            for (int r = rr; r < SROWS; r += 16) {
                const int ih = oh0 - 1 + r;
                const bool ok = (ih >= 0 && ih < 64);
                const int ihc = ok ? ih : 0;
                const uint32_t dst = (uint32_t)__cvta_generic_to_shared(
                    srow0 + r * 68 + c16 * 4);
                cp_async16(dst, g + ihc * 64 + c16 * 4, ok ? 16 : 0);
            }
        }
        for (int i = t; i < 288; i += 256) {
            const int co = i / 36;
            const int rem = i - co * 36;
            const int ci = rem / 9;
            const int k = rem - ci * 9;
            const uint32_t dst = (uint32_t)__cvta_generic_to_shared(
                sWBase + ((s * 8 + co) * 4 + ci) * 12 + k);
            cp_async4(dst, wb + ((size_t)co * Ci + cbase + ci) * 9 + k);
        }
    };

    const int nch = Ci >> 2;
    stage_chunk(0, 0);
    cp_commit();

    for (int c = 0; c < nch; c++) {
        cp_wait<0>();
        __syncthreads();
        if (c + 1 < nch) { stage_chunk(c + 1, (c + 1) & 1); cp_commit(); }

        const int s = c & 1;
        #pragma unroll 1
        for (int ci = 0; ci < 4; ci++) {
            const float* rowb = sInBase + (size_t)((s * 4 + ci) * SROWS) * 68;
            float iv[RPT + 2][6];
            #pragma unroll
            for (int r = 0; r < RPT + 2; r++) {
                const float* rp = rowb + (RPT * ty + r) * 68;
                const float4 a = *reinterpret_cast<const float4*>(rp + 4 * tx);
                const float lf = (tx == 0) ? rp[66] : rp[4 * tx - 1];
                const float rg = rp[4 * tx + 4];
                iv[r][0] = lf;  iv[r][1] = a.x; iv[r][2] = a.y;
                iv[r][3] = a.z; iv[r][4] = a.w; iv[r][5] = rg;
            }
            #pragma unroll
            for (int co = 0; co < 8; co++) {
                const float* wp = sWBase + ((s * 8 + co) * 4 + ci) * 12;
                const float4 w0 = *reinterpret_cast<const float4*>(wp);
                const float4 w1 = *reinterpret_cast<const float4*>(wp + 4);
                const float w8 = wp[8];
                const float wv[9] = {w0.x, w0.y, w0.z, w0.w,
                                     w1.x, w1.y, w1.z, w1.w, w8};
                #pragma unroll
                for (int r2 = 0; r2 < RPT; r2++)
                    #pragma unroll
                    for (int c2 = 0; c2 < 4; c2++) {
                        float a2 = acc[co][r2 * 4 + c2];
                        #pragma unroll
                        for (int kh = 0; kh < 3; kh++)
                            #pragma unroll
                            for (int kw = 0; kw < 3; kw++)
                                a2 = fmaf(iv[r2 + kh][c2 + kw],
                                          wv[kh * 3 + kw], a2);
                        acc[co][r2 * 4 + c2] = a2;
                    }
            }
        }
    }

    float* outb = out + ((size_t)n * Co + cog * 8) * 4096;
    #pragma unroll
    for (int co = 0; co < 8; co++) {
        const float b = BIAS ? bias[cog * 8 + co] : 0.0f;
        #pragma unroll
        for (int r2 = 0; r2 < RPT; r2++) {
            const int oh = oh0 + RPT * ty + r2;
            float4 v = make_float4(acc[co][r2 * 4 + 0] + b,
                                   acc[co][r2 * 4 + 1] + b,
                                   acc[co][r2 * 4 + 2] + b,
                                   acc[co][r2 * 4 + 3] + b);
            if (RELU) {
                v.x = fmaxf(v.x, 0.f); v.y = fmaxf(v.y, 0.f);
                v.z = fmaxf(v.z, 0.f); v.w = fmaxf(v.w, 0.f);
            }
            *reinterpret_cast<float4*>(
                outb + (size_t)co * 4096 + oh * 64 + 4 * tx) = v;
        }
    }
}

// ---------------------------------------------------------------------------
// 4x4 stride-2 pad-1 conv, cp.async double-buffered, single barrier/chunk.
// ---------------------------------------------------------------------------
#define K4P_SMEM ((2 * 66 * 136 + 2 * 8 * 16) * 4)

__global__ void __launch_bounds__(256, 2) conv4x4s2_pipe(
    const float* __restrict__ in, const float* __restrict__ w,
    const float* __restrict__ bias, float* __restrict__ out,
    int Ci, int Hi, int Wi, int Co, int ntx)
{
    extern __shared__ float sm[];
    float* sInB = sm;
    float* sWB = sm + 2 * 66 * 136;

    const int Ho = Hi >> 1, Wo = Wi >> 1;
    const int n = blockIdx.z;
    const int cog = blockIdx.y;
    const int tileY = blockIdx.x / ntx;
    const int tileX = blockIdx.x - tileY * ntx;
    const int oh0 = tileY * 32, ow0 = tileX * 64;
    const int t = threadIdx.x;
    const int tx = t & 15, ty = t >> 4;
    const int gc0 = 2 * ow0 - 4;

    float acc[8][8];
    #pragma unroll
    for (int i = 0; i < 8; i++)
        #pragma unroll
        for (int j = 0; j < 8; j++) acc[i][j] = 0.0f;

    const float* inb = in + (size_t)n * Ci * Hi * Wi;

    auto stage = [&](int ci, int s) {
        const float* g = inb + (size_t)ci * Hi * Wi;
        float* sIn = sInB + s * 66 * 136;
        for (int i = t; i < 66 * 34; i += 256) {
            const int r = i / 34;
            const int u = i - r * 34;
            const int ih = 2 * oh0 - 1 + r;
            const int gc = gc0 + 4 * u;
            const bool ok = (ih >= 0) && (ih < Hi) && (gc >= 0) && (gc + 3 < Wi);
            const int iha = ok ? ih : 0;
            const int gca = ok ? gc : 0;
            const uint32_t dst = (uint32_t)__cvta_generic_to_shared(
                sIn + r * 136 + 4 * u);
            cp_async16(dst, g + (size_t)iha * Wi + gca, ok ? 16 : 0);
        }
        if (t < 32) {
            const int co = t >> 2, quad = t & 3;
            const uint32_t dst = (uint32_t)__cvta_generic_to_shared(
                sWB + (s * 8 + co) * 16 + 4 * quad);
            cp_async16(dst,
                       w + ((size_t)(cog * 8 + co) * Ci + ci) * 16 + 4 * quad,
                       16);
        }
    };

    stage(0, 0);
    cp_commit();

    for (int ci = 0; ci < Ci; ci++) {
        cp_wait<0>();
        __syncthreads();
        if (ci + 1 < Ci) { stage(ci + 1, (ci + 1) & 1); cp_commit(); }

        const int s = ci & 1;
        const float* sIn = sInB + s * 66 * 136;
        #pragma unroll
        for (int kh = 0; kh < 4; kh++) {
            float iv[2][10];
            #pragma unroll
            for (int r2 = 0; r2 < 2; r2++) {
                const float* rp = sIn + (4 * ty + 2 * r2 + kh) * 136 + 8 * tx;
                const float s0 = rp[3];
                const float4 a = *reinterpret_cast<const float4*>(rp + 4);
                const float4 b = *reinterpret_cast<const float4*>(rp + 8);
                const float s1 = rp[12];
                iv[r2][0] = s0;  iv[r2][1] = a.x; iv[r2][2] = a.y;
                iv[r2][3] = a.z; iv[r2][4] = a.w; iv[r2][5] = b.x;
                iv[r2][6] = b.y; iv[r2][7] = b.z; iv[r2][8] = b.w;
                iv[r2][9] = s1;
            }
            #pragma unroll
            for (int co = 0; co < 8; co++) {
                const float4 wq = *reinterpret_cast<const float4*>(
                    sWB + (s * 8 + co) * 16 + kh * 4);
                const float wv[4] = {wq.x, wq.y, wq.z, wq.w};
                #pragma unroll
                for (int r2 = 0; r2 < 2; r2++)
                    #pragma unroll
                    for (int c2 = 0; c2 < 4; c2++) {
                        float a = acc[co][r2 * 4 + c2];
                        #pragma unroll
                        for (int kw = 0; kw < 4; kw++)
                            a = fmaf(iv[r2][2 * c2 + kw], wv[kw], a);
                        acc[co][r2 * 4 + c2] = a;
                    }
            }
        }
    }

    #pragma unroll
    for (int co = 0; co < 8; co++) {
        const float b = bias[cog * 8 + co];
        float* ob = out + ((size_t)n * Co + cog * 8 + co) * Ho * Wo;
        #pragma unroll
        for (int r2 = 0; r2 < 2; r2++) {
            const int oh = oh0 + 2 * ty + r2;
            const float4 v = make_float4(acc[co][r2 * 4 + 0] + b,
                                         acc[co][r2 * 4 + 1] + b,
                                         acc[co][r2 * 4 + 2] + b,
                                         acc[co][r2 * 4 + 3] + b);
            *reinterpret_cast<float4*>(
                ob + (size_t)oh * Wo + ow0 + 4 * tx) = v;
        }
    }
}

// ---------------------------------------------------------------------------
// 1x1 conv (fp32), unroll 4.
// ---------------------------------------------------------------------------
template <bool RELU, bool BIAS, bool RES>
__global__ void __launch_bounds__(256) conv1x1_k(
    const float* __restrict__ in, const float* __restrict__ w,
    const float* __restrict__ bias, const float* __restrict__ res,
    float* __restrict__ out, int Ci, int Co)
{
    __shared__ float sW1[8 * 128];
    const int n = blockIdx.z;
    const int cog = blockIdx.y;
    const int hw = blockIdx.x * 1024 + threadIdx.x * 4;
    const int t = threadIdx.x;

    for (int i = t; i < 8 * Ci; i += 256)
        sW1[i] = w[(size_t)cog * 8 * Ci + i];
    __syncthreads();

    const float* ip = in + (size_t)n * Ci * 4096 + hw;
    float4 acc[8];
    #pragma unroll
    for (int co = 0; co < 8; co++) acc[co] = make_float4(0.f, 0.f, 0.f, 0.f);

    #pragma unroll 4
    for (int ci = 0; ci < Ci; ci++) {
        const float4 xv = *reinterpret_cast<const float4*>(ip + (size_t)ci * 4096);
        #pragma unroll
        for (int co = 0; co < 8; co++) {
            const float wv = sW1[co * Ci + ci];
            acc[co].x = fmaf(xv.x, wv, acc[co].x);
            acc[co].y = fmaf(xv.y, wv, acc[co].y);
            acc[co].z = fmaf(xv.z, wv, acc[co].z);
            acc[co].w = fmaf(xv.w, wv, acc[co].w);
        }
    }

    #pragma unroll
    for (int co = 0; co < 8; co++) {
        float4 v = acc[co];
        if (BIAS) {
            const float b = bias[cog * 8 + co];
            v.x += b; v.y += b; v.z += b; v.w += b;
        }
        if (RELU) {
            v.x = fmaxf(v.x, 0.f); v.y = fmaxf(v.y, 0.f);
            v.z = fmaxf(v.z, 0.f); v.w = fmaxf(v.w, 0.f);
        }
        const size_t o = ((size_t)n * Co + cog * 8 + co) * 4096 + hw;
        if (RES) {
            const float4 r = *reinterpret_cast<const float4*>(res + o);
            v.x += r.x; v.y += r.y; v.z += r.z; v.w += r.w;
        }
        *reinterpret_cast<float4*>(out + o) = v;
    }
}

// ---------------------------------------------------------------------------
// Transposed conv k4 s2 p1, cp.async double-buffered. Optional fused
// reconstruction loss (LOSS=true: accumulate (out - ref)^2 into g_rec_loss).
// ---------------------------------------------------------------------------
#define DC_SMEM(CO_T) ((2 * 8 * 18 * 44 + 2 * 8 * (CO_T) * 16) * 4)

template <int CO_T, bool LOSS>
__global__ void __launch_bounds__(256, 2) deconv4x4s2_pipe(
    const float* __restrict__ in, const float* __restrict__ w,
    const float* __restrict__ bias, float* __restrict__ out,
    const float* __restrict__ ref,
    int Ci, int Hi, int Wi, int Co)
{
    extern __shared__ float sm[];
    float* sInB = sm;
    float* sWB = sm + 2 * 8 * 18 * 44;

    const int n = blockIdx.z;
    const int cog = blockIdx.y;
    const int ntx = Wi >> 5;
    const int tileY = blockIdx.x / ntx;
    const int tileX = blockIdx.x - tileY * ntx;
    const int i0 = tileY * 16, j0 = tileX * 32;
    const int t = threadIdx.x;
    const int tx = t & 15, ty = t >> 4;
    const int gc0 = j0 - 4;

    float acc[CO_T][2][4];
    #pragma unroll
    for (int c = 0; c < CO_T; c++)
        #pragma unroll
        for (int a = 0; a < 2; a++)
            #pragma unroll
            for (int j = 0; j < 4; j++) acc[c][a][j] = 0.0f;

    const float* inb = in + (size_t)n * Ci * Hi * Wi;

    const int RR[2][2] = {{1, 0}, {2, 1}};
    const int KH[2][2] = {{1, 3}, {0, 2}};
    const int CC[2][2] = {{1, 0}, {2, 1}};
    const int KW[2][2] = {{1, 3}, {0, 2}};

    auto stage = [&](int chunk, int s) {
        const int cb = chunk * 8;
        for (int i = t; i < 8 * 18 * 10; i += 256) {
            const int ci = i / 180;
            const int rem = i - ci * 180;
            const int r = rem / 10;
            const int u = rem - r * 10;
            const int ih = i0 - 1 + r;
            const int gc = gc0 + 4 * u;
            const bool ok = (ih >= 0) && (ih < Hi) && (gc >= 0) && (gc + 3 < Wi);
            const int iha = ok ? ih : 0;
            const int gca = ok ? gc : 0;
            const uint32_t dst = (uint32_t)__cvta_generic_to_shared(
                sInB + ((s * 8 + ci) * 18 + r) * 44 + 4 * u);
            cp_async16(dst, inb + (size_t)(cb + ci) * Hi * Wi +
                            (size_t)iha * Wi + gca, ok ? 16 : 0);
        }
        for (int i = t; i < 8 * CO_T * 4; i += 256) {
            const int ci = i / (CO_T * 4);
            const int rem = i - ci * (CO_T * 4);
            const int co = rem >> 2;
            const int quad = rem & 3;
            const uint32_t dst = (uint32_t)__cvta_generic_to_shared(
                sWB + ((s * 8 + ci) * CO_T + co) * 16 + 4 * quad);
            cp_async16(dst,
                       w + (((size_t)(cb + ci)) * Co + cog * CO_T + co) * 16 +
                           4 * quad, 16);
        }
    };

    const int nch = Ci >> 3;
    stage(0, 0);
    cp_commit();

    for (int c = 0; c < nch; c++) {
        cp_wait<0>();
        __syncthreads();
        if (c + 1 < nch) { stage(c + 1, (c + 1) & 1); cp_commit(); }

        const int s = c & 1;
        #pragma unroll 1
        for (int ci = 0; ci < 8; ci++) {
            const float* rowb = sInB + (size_t)((s * 8 + ci) * 18) * 44;
            float iv[3][4];
            #pragma unroll
            for (int r = 0; r < 3; r++) {
                const float* rp = rowb + (ty + r) * 44 + 3 + 2 * tx;
                iv[r][0] = rp[0]; iv[r][1] = rp[1];
                iv[r][2] = rp[2]; iv[r][3] = rp[3];
            }
            #pragma unroll
            for (int co = 0; co < CO_T; co++) {
                const float* wp = sWB + ((s * 8 + ci) * CO_T + co) * 16;
                const float4 q0 = *reinterpret_cast<const float4*>(wp);
                const float4 q1 = *reinterpret_cast<const float4*>(wp + 4);
                const float4 q2 = *reinterpret_cast<const float4*>(wp + 8);
                const float4 q3 = *reinterpret_cast<const float4*>(wp + 12);
                float wv[16] = {q0.x, q0.y, q0.z, q0.w, q1.x, q1.y, q1.z, q1.w,
                                q2.x, q2.y, q2.z, q2.w, q3.x, q3.y, q3.z, q3.w};
                #pragma unroll
                for (int q = 0; q < 2; q++)
                    #pragma unroll
                    for (int a = 0; a < 2; a++)
                        #pragma unroll
                        for (int b = 0; b < 2; b++) {
                            float sv = acc[co][a][2 * q + b];
                            #pragma unroll
                            for (int si = 0; si < 2; si++)
                                #pragma unroll
                                for (int ti = 0; ti < 2; ti++)
                                    sv = fmaf(iv[RR[a][si]][q + CC[b][ti]],
                                              wv[KH[a][si] * 4 + KW[b][ti]], sv);
                            acc[co][a][2 * q + b] = sv;
                        }
            }
        }
    }

    const int Ho = 2 * Hi, Wo = 2 * Wi;
    const int ow = 2 * j0 + 4 * tx;
    float lsum = 0.0f;
    #pragma unroll
    for (int co = 0; co < CO_T; co++) {
        const float b = bias[cog * CO_T + co];
        float* ob = out + ((size_t)n * Co + cog * CO_T + co) * Ho * Wo;
        #pragma unroll
        for (int a = 0; a < 2; a++) {
            const int oh = 2 * (i0 + ty) + a;
            const float4 v = make_float4(acc[co][a][0] + b, acc[co][a][1] + b,
                                         acc[co][a][2] + b, acc[co][a][3] + b);
            *reinterpret_cast<float4*>(ob + (size_t)oh * Wo + ow) = v;
            if (LOSS) {
                const float4 r4 = *reinterpret_cast<const float4*>(
                    ref + ((size_t)n * Co + cog * CO_T + co) * Ho * Wo +
                    (size_t)oh * Wo + ow);
                const float d0 = v.x - r4.x, d1 = v.y - r4.y;
                const float d2 = v.z - r4.z, d3 = v.w - r4.w;
                lsum = fmaf(d0, d0, lsum);
                lsum = fmaf(d1, d1, lsum);
                lsum = fmaf(d2, d2, lsum);
                lsum = fmaf(d3, d3, lsum);
            }
        }
    }
    if (LOSS) {
        __syncthreads();
        const float bsum = blockReduceSum(lsum);
        if (t == 0) atomicAdd(&g_rec_loss, (double)bsum);
    }
}

// ---------------------------------------------------------------------------
// Persistent VQ: grid 148 x 256 threads; codebook staged once per block,
// positions looped with stride gridDim*blockDim.
// ---------------------------------------------------------------------------
#define VQ_K 512
#define VQ_D 64
#define VQ_SMEM ((VQ_K * VQ_D + VQ_K) * 4)

__global__ void __launch_bounds__(256) vq_kernel(
    const float* __restrict__ z, const float* __restrict__ cb,
    float* __restrict__ q)
{
    extern __shared__ float smem[];
    float* scb = smem;
    float* snorm = smem + VQ_K * VQ_D;

    for (int i = threadIdx.x; i < VQ_K * VQ_D; i += blockDim.x)
        scb[i] = cb[i];
    __syncthreads();
    for (int c = threadIdx.x; c < VQ_K; c += blockDim.x) {
        float s = 0.0f;
        const float* cp = scb + c * VQ_D;
        #pragma unroll 16
        for (int d = 0; d < VQ_D; d++) s = fmaf(cp[d], cp[d], s);
        snorm[c] = s;
    }
    __syncthreads();

    float lsum = 0.0f;
    const int stride = gridDim.x * blockDim.x;
    for (int pos = blockIdx.x * blockDim.x + threadIdx.x; pos < 65536;
         pos += stride) {
        const int n = pos >> 12;
        const int hw = pos & 4095;

        float zv[VQ_D];
        const float* zp = z + (size_t)n * VQ_D * 4096 + hw;
        float zn = 0.0f;
        #pragma unroll
        for (int d = 0; d < VQ_D; d++) {
            zv[d] = zp[(size_t)d * 4096];
            zn = fmaf(zv[d], zv[d], zn);
        }

        float bestd = 3.402823466e+38f;
        int besti = 0;
        for (int c = 0; c < VQ_K; c++) {
            const float4* cp4 = reinterpret_cast<const float4*>(scb + c * VQ_D);
            float dot = 0.0f;
            #pragma unroll
            for (int d4 = 0; d4 < VQ_D / 4; d4++) {
                const float4 cv = cp4[d4];
                dot = fmaf(zv[4 * d4 + 0], cv.x, dot);
                dot = fmaf(zv[4 * d4 + 1], cv.y, dot);
                dot = fmaf(zv[4 * d4 + 2], cv.z, dot);
                dot = fmaf(zv[4 * d4 + 3], cv.w, dot);
            }
            const float dist = zn - 2.0f * dot + snorm[c];
            if (dist < bestd) { bestd = dist; besti = c; }
        }

        const float* cp = scb + besti * VQ_D;
        float* qp = q + (size_t)n * VQ_D * 4096 + hw;
        #pragma unroll
        for (int d = 0; d < VQ_D; d++) {
            const float cv = cp[d];
            qp[(size_t)d * 4096] = cv;
            const float df = zv[d] - cv;
            lsum = fmaf(df, df, lsum);
        }
    }
    const float bsum = blockReduceSum(lsum);
    if (threadIdx.x == 0) atomicAdd(&g_vq_loss, (double)bsum);
}

__global__ void finalize_kernel(float* out, int out_size) {
    const double recon = g_rec_loss / 3145728.0;
    const double vq = g_vq_loss / 4194304.0;
    out[out_size - 2] = (float)(recon + 1.25 * vq);
    out[out_size - 1] = (float)recon;
}

// ---------------------------------------------------------------------------
extern "C" void kernel_launch(void* const* d_in, const int* in_sizes, int n_in,
                              void* d_out, int out_size)
{
    const float* inp        = (const float*)d_in[0];
    const float* enc_w1     = (const float*)d_in[1];
    const float* enc_b1     = (const float*)d_in[2];
    const float* enc_w2     = (const float*)d_in[3];
    const float* enc_b2     = (const float*)d_in[4];
    const float* enc_w3     = (const float*)d_in[5];
    const float* enc_b3     = (const float*)d_in[6];
    const float* enc_res_w1 = (const float*)d_in[7];
    const float* enc_res_w2 = (const float*)d_in[8];
    const float* vq_w       = (const float*)d_in[9];
    const float* vq_b       = (const float*)d_in[10];
    const float* codebook   = (const float*)d_in[11];
    const float* dec_w1     = (const float*)d_in[12];
    const float* dec_b1     = (const float*)d_in[13];
    const float* dec_res_w1 = (const float*)d_in[14];
    const float* dec_res_w2 = (const float*)d_in[15];
    const float* dec_w2t    = (const float*)d_in[16];
    const float* dec_b2     = (const float*)d_in[17];
    const float* dec_w3t    = (const float*)d_in[18];
    const float* dec_b3     = (const float*)d_in[19];

    float *bufA, *bufB, *bufC, *half, *zb, *qb, *d1, *d2, *eb;
    cudaGetSymbolAddress((void**)&bufA, g_bufA);
    cudaGetSymbolAddress((void**)&bufB, g_bufB);
    cudaGetSymbolAddress((void**)&bufC, g_bufC);
    cudaGetSymbolAddress((void**)&half, g_half);
    cudaGetSymbolAddress((void**)&zb, g_z);
    cudaGetSymbolAddress((void**)&qb, g_q);
    cudaGetSymbolAddress((void**)&d1, g_d1);
    cudaGetSymbolAddress((void**)&d2, g_d2);
    cudaGetSymbolAddress((void**)&eb, g_e);

    cudaFuncSetAttribute(vq_kernel, cudaFuncAttributeMaxDynamicSharedMemorySize,
                         VQ_SMEM);
    cudaFuncSetAttribute(conv4x4s2_pipe,
                         cudaFuncAttributeMaxDynamicSharedMemorySize, K4P_SMEM);
    cudaFuncSetAttribute(conv3x3_pipe<2, false, true>,
                         cudaFuncAttributeMaxDynamicSharedMemorySize,
                         C3P_SMEM(2));
    cudaFuncSetAttribute(conv3x3_pipe<2, true, false>,
                         cudaFuncAttributeMaxDynamicSharedMemorySize,
                         C3P_SMEM(2));
    cudaFuncSetAttribute(conv3x3_pipe<1, true, false>,
                         cudaFuncAttributeMaxDynamicSharedMemorySize,
                         C3P_SMEM(1));
    cudaFuncSetAttribute(deconv4x4s2_pipe<4, false>,
                         cudaFuncAttributeMaxDynamicSharedMemorySize,
                         DC_SMEM(4));
    cudaFuncSetAttribute(deconv4x4s2_pipe<3, true>,
                         cudaFuncAttributeMaxDynamicSharedMemorySize,
                         DC_SMEM(3));

    zero_losses_kernel<<<1, 1>>>();

    // ---- Encoder ----
    conv4x4s2_pipe<<<dim3(8, 8, NB), 256, K4P_SMEM>>>(
        inp, enc_w1, enc_b1, bufA, 3, 256, 256, 64, 2);
    conv4x4s2_pipe<<<dim3(2, 16, NB), 256, K4P_SMEM>>>(
        bufA, enc_w2, enc_b2, bufB, 64, 128, 128, 128, 1);
    conv3x3_pipe<2, false, true><<<dim3(2, 16, NB), 256, C3P_SMEM(2)>>>(
        bufB, enc_w3, enc_b3, bufC, 128, 128);

    {
        float* cur = bufC;
        float* alt = bufB;
        for (int i = 0; i < 3; i++) {
            conv3x3_pipe<2, true, false><<<dim3(2, 8, NB), 256, C3P_SMEM(2)>>>(
                cur, enc_res_w1 + (size_t)i * 64 * 128 * 9, nullptr, half,
                128, 64);
            conv1x1_k<true, false, true><<<dim3(4, 16, NB), 256>>>(
                half, enc_res_w2 + (size_t)i * 128 * 64, nullptr, cur, alt,
                64, 128);
            float* t = cur; cur = alt; alt = t;
        }
        conv1x1_k<false, true, false><<<dim3(4, 8, NB), 256>>>(
            cur, vq_w, vq_b, nullptr, zb, 128, 64);
    }

    // ---- VQ (persistent, grid 148) ----
    vq_kernel<<<148, 256, VQ_SMEM>>>(zb, codebook, qb);

    // ---- Decoder ----
    conv3x3_pipe<2, false, true><<<dim3(2, 8, NB), 256, C3P_SMEM(2)>>>(
        qb, dec_w1, dec_b1, d1, 64, 64);
    {
        float* cur = d1;
        float* alt = d2;
        for (int i = 0; i < 3; i++) {
            conv3x3_pipe<1, true, false><<<dim3(4, 4, NB), 256, C3P_SMEM(1)>>>(
                cur, dec_res_w1 + (size_t)i * 32 * 64 * 9, nullptr, half,
                64, 32);
            conv1x1_k<true, false, true><<<dim3(4, 8, NB), 256>>>(
                half, dec_res_w2 + (size_t)i * 64 * 32, nullptr, cur, alt,
                32, 64);
            float* t = cur; cur = alt; alt = t;
        }
        deconv4x4s2_pipe<4, false><<<dim3(8, 8, NB), 256, DC_SMEM(4)>>>(
            cur, dec_w2t, dec_b2, eb, nullptr, 64, 64, 64, 32);
    }
    // deconv2 with fused reconstruction loss
    deconv4x4s2_pipe<3, true><<<dim3(32, 1, NB), 256, DC_SMEM(3)>>>(
        eb, dec_w3t, dec_b3, (float*)d_out, inp, 32, 128, 128, 3);

    finalize_kernel<<<1, 1>>>((float*)d_out, out_size);
}